// round 14
// baseline (speedup 1.0000x reference)
#include <cuda_runtime.h>
#include <cuda_bf16.h>
#include <math.h>
#include <stdint.h>

#define NN 2048
#define EE 32768
#define DD 256
#define HH 8
#define HDm 32
#define DFF 1024
#define MAXD 512

// ---------------- scratch (device globals; zero-initialized at load) ----------------
__device__ float    g_Q[NN * DD];
__device__ float    g_K[NN * DD];
__device__ float    g_V[NN * DD];
__device__ float    g_proj[4 * NN * DD];     // Wo split-K slices
__device__ float    g_h1[NN * DD];
__device__ float    g_f2[4 * NN * DD];       // FFN2 split-K slices
__device__ float    g_ebias[EE * HH];
__device__ unsigned g_adj[NN * NN / 32];
__device__ unsigned g_hasb[NN * NN / 32];
__device__ int      g_bidx[NN * NN];

// bf16 hi/lo pairs (pre-split fp32)
__device__ __nv_bfloat16 g_nfH[NN * DD],  g_nfL[NN * DD];
__device__ __nv_bfloat16 g_WqH[DD * DD],  g_WqL[DD * DD];
__device__ __nv_bfloat16 g_WkH[DD * DD],  g_WkL[DD * DD];
__device__ __nv_bfloat16 g_WvH[DD * DD],  g_WvL[DD * DD];
__device__ __nv_bfloat16 g_WoH[DD * DD],  g_WoL[DD * DD];
__device__ __nv_bfloat16 g_W1H[DD * DFF], g_W1L[DD * DFF];
__device__ __nv_bfloat16 g_W2H[DFF * DD], g_W2L[DFF * DD];
__device__ __nv_bfloat16 g_attH[NN * DD], g_attL[NN * DD];
__device__ __nv_bfloat16 g_h1H[NN * DD],  g_h1L[NN * DD];
__device__ __nv_bfloat16 g_f1H[NN * DFF], g_f1L[NN * DFF];

// ---------------- helpers ----------------
__device__ __forceinline__ uint32_t smem_u32(const void* p) {
    uint32_t a;
    asm("{ .reg .u64 t; cvta.to.shared.u64 t, %1; cvt.u32.u64 %0, t; }" : "=r"(a) : "l"(p));
    return a;
}
__device__ __forceinline__ void mma_bf16(float* d, const uint32_t* a, const uint32_t* b) {
    asm volatile(
        "mma.sync.aligned.m16n8k16.row.col.f32.bf16.bf16.f32 "
        "{%0,%1,%2,%3}, {%4,%5,%6,%7}, {%8,%9}, {%0,%1,%2,%3};"
        : "+f"(d[0]), "+f"(d[1]), "+f"(d[2]), "+f"(d[3])
        : "r"(a[0]), "r"(a[1]), "r"(a[2]), "r"(a[3]), "r"(b[0]), "r"(b[1]));
}
#define LDSM4(d0, d1, d2, d3, a) \
    asm volatile("ldmatrix.sync.aligned.m8n8.x4.shared.b16 {%0,%1,%2,%3},[%4];" \
        : "=r"(d0), "=r"(d1), "=r"(d2), "=r"(d3) : "r"(a))
#define LDSM4T(d0, d1, d2, d3, a) \
    asm volatile("ldmatrix.sync.aligned.m8n8.x4.trans.shared.b16 {%0,%1,%2,%3},[%4];" \
        : "=r"(d0), "=r"(d1), "=r"(d2), "=r"(d3) : "r"(a))
#define CP16(dst, src) \
    asm volatile("cp.async.ca.shared.global [%0], [%1], 16;" :: "r"(dst), "l"(src))
#define CPCOMMIT() asm volatile("cp.async.commit_group;" ::: "memory")
#define CPWAIT0()  asm volatile("cp.async.wait_group 0;" ::: "memory")

__device__ __forceinline__ uint32_t pack_hi(float f0, float f1) {
    __nv_bfloat16 h0 = __float2bfloat16(f0), h1 = __float2bfloat16(f1);
    return (uint32_t)__bfloat16_as_ushort(h0) | ((uint32_t)__bfloat16_as_ushort(h1) << 16);
}
__device__ __forceinline__ uint32_t pack_lo(float f0, float f1) {
    __nv_bfloat16 h0 = __float2bfloat16(f0), h1 = __float2bfloat16(f1);
    __nv_bfloat16 l0 = __float2bfloat16(f0 - __bfloat162float(h0));
    __nv_bfloat16 l1 = __float2bfloat16(f1 - __bfloat162float(h1));
    return (uint32_t)__bfloat16_as_ushort(l0) | ((uint32_t)__bfloat16_as_ushort(l1) << 16);
}

// ====== GEMM: 64x64 tile, BK=32, 4 warps, cp.async 2-buffer pipeline, ldmatrix ======
// flags: 1=RELU, 2=SPLITK (slice -> C + z*NN*N, no bias), 4=OUT_PAIR, 8=z selects weight set
#define ASTR 40
#define BSTR 72
#define ABUF (64 * ASTR)
#define BBUF (32 * BSTR)

__global__ void __launch_bounds__(128) gemm_tc(
    const __nv_bfloat16* __restrict__ AH, const __nv_bfloat16* __restrict__ AL,
    const __nv_bfloat16* __restrict__ BH0, const __nv_bfloat16* __restrict__ BH1, const __nv_bfloat16* __restrict__ BH2,
    const __nv_bfloat16* __restrict__ BL0, const __nv_bfloat16* __restrict__ BL1, const __nv_bfloat16* __restrict__ BL2,
    const float* __restrict__ bias0, const float* __restrict__ bias1, const float* __restrict__ bias2,
    float* __restrict__ C0, float* __restrict__ C1, float* __restrict__ C2,
    __nv_bfloat16* __restrict__ CH, __nv_bfloat16* __restrict__ CL,
    int K, int N, int flags)
{
    __shared__ __align__(16) __nv_bfloat16 AsH[2][ABUF];
    __shared__ __align__(16) __nv_bfloat16 AsL[2][ABUF];
    __shared__ __align__(16) __nv_bfloat16 BsH[2][BBUF];
    __shared__ __align__(16) __nv_bfloat16 BsL[2][BBUF];

    const __nv_bfloat16* BH = BH0; const __nv_bfloat16* BL = BL0;
    const float* bias = bias0; float* C = C0;
    int kslice = 0, nsl = 1;
    if (flags & 8) {
        if (blockIdx.z == 1) { BH = BH1; BL = BL1; bias = bias1; C = C1; }
        else if (blockIdx.z == 2) { BH = BH2; BL = BL2; bias = bias2; C = C2; }
    } else if (flags & 2) {
        kslice = blockIdx.z; nsl = gridDim.z;
        C = C0 + (size_t)kslice * NN * N;
    }

    const int tid = threadIdx.x;
    const int lane = tid & 31;
    const int wid = tid >> 5;
    const int wm = wid >> 1, wn = wid & 1;
    const int g = lane >> 2, tg = lane & 3;
    const int m0 = blockIdx.y * 64;
    const int n0 = blockIdx.x * 64;

    const int nk = (K >> 5) / nsl;
    const int kstart = kslice * nk;

    float acc[2][4][4];
#pragma unroll
    for (int i = 0; i < 2; i++)
#pragma unroll
        for (int j = 0; j < 4; j++)
#pragma unroll
            for (int c = 0; c < 4; c++) acc[i][j][c] = 0.f;

    // cp.async per-thread coords: A 64x32 (16 elems/thr), B 32x64 (16 elems/thr)
    const int ar = tid >> 1, ac = (tid & 1) * 16;
    const int bk = tid >> 2, bn = (tid & 3) * 16;
    const uint32_t aso = (uint32_t)(ar * ASTR + ac) * 2;
    const uint32_t bso = (uint32_t)(bk * BSTR + bn) * 2;
    const uint32_t aSH[2] = { smem_u32(AsH[0]) + aso, smem_u32(AsH[1]) + aso };
    const uint32_t aSL[2] = { smem_u32(AsL[0]) + aso, smem_u32(AsL[1]) + aso };
    const uint32_t bSH[2] = { smem_u32(BsH[0]) + bso, smem_u32(BsH[1]) + bso };
    const uint32_t bSL[2] = { smem_u32(BsL[0]) + bso, smem_u32(BsL[1]) + bso };

#define LOADC(KC, BUF) do { \
    const __nv_bfloat16* gA = AH + (size_t)(m0 + ar) * K + (KC) * 32 + ac; \
    const __nv_bfloat16* gAl = AL + (size_t)(m0 + ar) * K + (KC) * 32 + ac; \
    CP16(aSH[BUF], gA);       CP16(aSH[BUF] + 16, gA + 8); \
    CP16(aSL[BUF], gAl);      CP16(aSL[BUF] + 16, gAl + 8); \
    const __nv_bfloat16* gB = BH + (size_t)((KC) * 32 + bk) * N + n0 + bn; \
    const __nv_bfloat16* gBl = BL + (size_t)((KC) * 32 + bk) * N + n0 + bn; \
    CP16(bSH[BUF], gB);       CP16(bSH[BUF] + 16, gB + 8); \
    CP16(bSL[BUF], gBl);      CP16(bSL[BUF] + 16, gBl + 8); \
    CPCOMMIT(); \
} while (0)

    const uint32_t aOff = (((wm * 32 + (lane & 15)) * ASTR + ((lane >> 4) << 3)) << 1);
    const uint32_t bOff = ((((lane & 15)) * BSTR + wn * 32 + ((lane >> 4) << 3)) << 1);
    const uint32_t aBH[2] = { smem_u32(AsH[0]) + aOff, smem_u32(AsH[1]) + aOff };
    const uint32_t aBL[2] = { smem_u32(AsL[0]) + aOff, smem_u32(AsL[1]) + aOff };
    const uint32_t bBH[2] = { smem_u32(BsH[0]) + bOff, smem_u32(BsH[1]) + bOff };
    const uint32_t bBL[2] = { smem_u32(BsL[0]) + bOff, smem_u32(BsL[1]) + bOff };

    LOADC(kstart, 0);

    int buf = 0;
    for (int kc = 0; kc < nk; kc++, buf ^= 1) {
        CPWAIT0();            // group for chunk kc complete
        __syncthreads();      // smem visible; all warps done with compute(kc-1)
        if (kc + 1 < nk) LOADC(kstart + kc + 1, buf ^ 1);   // async, overlaps MMA

        const uint32_t aH = aBH[buf], aL = aBL[buf];
        const uint32_t bH = bBH[buf], bL = bBL[buf];
#pragma unroll
        for (int kk = 0; kk < 2; kk++) {
            const int kb = kk * 16;
            uint32_t ah[2][4], al[2][4], bh[4][2], bl[4][2];
            LDSM4(ah[0][0], ah[0][1], ah[0][2], ah[0][3], aH + (kb << 1));
            LDSM4(ah[1][0], ah[1][1], ah[1][2], ah[1][3], aH + ((16 * ASTR + kb) << 1));
            LDSM4(al[0][0], al[0][1], al[0][2], al[0][3], aL + (kb << 1));
            LDSM4(al[1][0], al[1][1], al[1][2], al[1][3], aL + ((16 * ASTR + kb) << 1));
            LDSM4T(bh[0][0], bh[0][1], bh[1][0], bh[1][1], bH + ((kb * BSTR) << 1));
            LDSM4T(bh[2][0], bh[2][1], bh[3][0], bh[3][1], bH + ((kb * BSTR + 16) << 1));
            LDSM4T(bl[0][0], bl[0][1], bl[1][0], bl[1][1], bL + ((kb * BSTR) << 1));
            LDSM4T(bl[2][0], bl[2][1], bl[3][0], bl[3][1], bL + ((kb * BSTR + 16) << 1));
#pragma unroll
            for (int i = 0; i < 2; i++)
#pragma unroll
                for (int j = 0; j < 4; j++) mma_bf16(acc[i][j], ah[i], bh[j]);
#pragma unroll
            for (int i = 0; i < 2; i++)
#pragma unroll
                for (int j = 0; j < 4; j++) mma_bf16(acc[i][j], ah[i], bl[j]);
#pragma unroll
            for (int i = 0; i < 2; i++)
#pragma unroll
                for (int j = 0; j < 4; j++) mma_bf16(acc[i][j], al[i], bh[j]);
        }
    }

    // ---- epilogue ----
#pragma unroll
    for (int i = 0; i < 2; i++) {
        int row = m0 + wm * 32 + i * 16 + g;
#pragma unroll
        for (int j = 0; j < 4; j++) {
            int col = n0 + wn * 32 + j * 8 + tg * 2;
            float v0 = acc[i][j][0], v1 = acc[i][j][1], v2 = acc[i][j][2], v3 = acc[i][j][3];
            if (flags & 2) {
                *(float2*)(C + (size_t)row * N + col) = make_float2(v0, v1);
                *(float2*)(C + (size_t)(row + 8) * N + col) = make_float2(v2, v3);
            } else {
                float b0f = bias[col], b1f = bias[col + 1];
                v0 += b0f; v1 += b1f; v2 += b0f; v3 += b1f;
                if (flags & 1) {
                    v0 = fmaxf(v0, 0.f); v1 = fmaxf(v1, 0.f);
                    v2 = fmaxf(v2, 0.f); v3 = fmaxf(v3, 0.f);
                }
                if (flags & 4) {
                    *(uint32_t*)&CH[(size_t)row * N + col] = pack_hi(v0, v1);
                    *(uint32_t*)&CL[(size_t)row * N + col] = pack_lo(v0, v1);
                    *(uint32_t*)&CH[(size_t)(row + 8) * N + col] = pack_hi(v2, v3);
                    *(uint32_t*)&CL[(size_t)(row + 8) * N + col] = pack_lo(v2, v3);
                } else {
                    *(float2*)(C + (size_t)row * N + col) = make_float2(v0, v1);
                    *(float2*)(C + (size_t)(row + 8) * N + col) = make_float2(v2, v3);
                }
            }
        }
    }
}

// -------- merged prep (fp32 -> bf16 hi/lo) + edge-bias + scatter (one launch) --------
__global__ void prep_scatter_kernel(
    const float* __restrict__ nf,
    const float* __restrict__ Wq, const float* __restrict__ Wk,
    const float* __restrict__ Wv, const float* __restrict__ Wo,
    const float* __restrict__ W1, const float* __restrict__ W2,
    const int* __restrict__ src, const int* __restrict__ dst,
    const float* __restrict__ ef,
    const float* __restrict__ We, const float* __restrict__ be)
{
    int t = blockIdx.x * 256 + threadIdx.x;

    if (t < EE) {
        const float* row = ef + t * 10;
        float r[10];
#pragma unroll
        for (int k = 0; k < 10; k++) r[k] = row[k];
#pragma unroll
        for (int h = 0; h < HH; h++) {
            float s = be[h];
#pragma unroll
            for (int k = 0; k < 10; k++) s = fmaf(r[k], We[k * HH + h], s);
            g_ebias[t * HH + h] = s;
        }
        int s = src[t], d = dst[t];
        int p1 = s * NN + d;
        int p2 = d * NN + s;
        atomicOr(&g_adj[p1 >> 5], 1u << (p1 & 31));
        atomicOr(&g_adj[p2 >> 5], 1u << (p2 & 31));
        atomicOr(&g_hasb[p1 >> 5], 1u << (p1 & 31));
        atomicMax(&g_bidx[p1], t);
    } else if (t < EE + NN) {
        int i = t - EE;
        int p = i * NN + i;
        atomicOr(&g_adj[p >> 5], 1u << (p & 31));
    }

    const float* s; __nv_bfloat16 *dh, *dl; int off;
    if      (t <  524288) { s = nf; dh = g_nfH; dl = g_nfL; off = t; }
    else if (t <  589824) { s = Wq; dh = g_WqH; dl = g_WqL; off = t - 524288; }
    else if (t <  655360) { s = Wk; dh = g_WkH; dl = g_WkL; off = t - 589824; }
    else if (t <  720896) { s = Wv; dh = g_WvH; dl = g_WvL; off = t - 655360; }
    else if (t <  786432) { s = Wo; dh = g_WoH; dl = g_WoL; off = t - 720896; }
    else if (t < 1048576) { s = W1; dh = g_W1H; dl = g_W1L; off = t - 786432; }
    else if (t < 1310720) { s = W2; dh = g_W2H; dl = g_W2L; off = t - 1048576; }
    else return;
    float v = s[off];
    __nv_bfloat16 h = __float2bfloat16(v);
    dh[off] = h;
    dl[off] = __float2bfloat16(v - __bfloat162float(h));
}

// ------- sparse attention: three-pass softmax; Pass C vectorized (float4 V) -------
__global__ void __launch_bounds__(256) attn_kernel() {
    const int i = blockIdx.x;
    const int tid = threadIdx.x;
    const int lane = tid & 31;
    const int h = tid >> 5;
    const int b = lane >> 2;
    const int dg = lane & 3;
    const int ng = lane >> 3;
    const int dq = lane & 7;

    __shared__ unsigned adjw[64];
    __shared__ int wbase[64];
    __shared__ int s_deg;
    __shared__ short jlist[2048 + 8];
    __shared__ short eidx[2048 + 8];
    __shared__ __align__(16) float qs[DD];
    __shared__ float sc_s[HH][MAXD];

    if (tid < 64) adjw[tid] = g_adj[i * 64 + tid];
    qs[tid] = g_Q[i * DD + tid];
    __syncthreads();

    if (tid < 32) {
        int c0 = __popc(adjw[2 * tid]), c1 = __popc(adjw[2 * tid + 1]);
        int s = c0 + c1, scan = s;
#pragma unroll
        for (int o = 1; o < 32; o <<= 1) {
            int v = __shfl_up_sync(0xffffffffu, scan, o);
            if (tid >= o) scan += v;
        }
        int excl = scan - s;
        wbase[2 * tid] = excl;
        wbase[2 * tid + 1] = excl + c0;
        if (tid == 31) s_deg = scan;
    }
    __syncthreads();
    if (tid < 64) {
        unsigned w = adjw[tid];
        int off = wbase[tid];
        while (w) {
            int bb = __ffs(w) - 1; w &= w - 1;
            int j = tid * 32 + bb;
            jlist[off] = (short)j;
            int p = i * NN + j;
            eidx[off] = ((g_hasb[p >> 5] >> (p & 31)) & 1u) ? (short)g_bidx[p] : (short)-1;
            off++;
        }
    }
    __syncthreads();
    const int deg = s_deg;
    if (tid < 8) { jlist[deg + tid] = jlist[0]; eidx[deg + tid] = -1; }
    __syncthreads();

    const float scale = 0.17677669529663687f;
    const float4* q4 = (const float4*)(qs + h * HDm + dg * 8);
    const float4 q0 = q4[0], q1 = q4[1];

    if (deg <= MAXD) {
        float mlane = -1e30f;
        for (int base = 0; base < deg; base += 8) {
            int j = jlist[base + b];
            const float4* kr = (const float4*)(g_K + (size_t)j * DD + h * HDm + dg * 8);
            float4 k0 = kr[0], k1 = kr[1];
            float s = q0.x * k0.x + q0.y * k0.y + q0.z * k0.z + q0.w * k0.w
                    + q1.x * k1.x + q1.y * k1.y + q1.z * k1.z + q1.w * k1.w;
            s += __shfl_xor_sync(0xffffffffu, s, 1);
            s += __shfl_xor_sync(0xffffffffu, s, 2);
            s *= scale;
            int ei = eidx[base + b];
            if (ei >= 0) s += g_ebias[ei * HH + h];
            if (base + b >= deg) s = -1e30f;
            mlane = fmaxf(mlane, s);
            if (dg == 0) sc_s[h][base + b] = s;
        }
#pragma unroll
        for (int o = 16; o > 0; o >>= 1)
            mlane = fmaxf(mlane, __shfl_xor_sync(0xffffffffu, mlane, o));
        const float m = mlane;

        const int degPad = (deg + 7) & ~7;
        float lsum = 0.f;
        for (int base = 0; base < degPad; base += 32) {
            int idx = base + lane;
            if (idx < degPad) {
                float e = (idx < deg) ? __expf(sc_s[h][idx] - m) : 0.f;
                sc_s[h][idx] = e;
                lsum += e;
            }
        }
#pragma unroll
        for (int o = 16; o > 0; o >>= 1) lsum += __shfl_xor_sync(0xffffffffu, lsum, o);

        float4 acc4 = make_float4(0.f, 0.f, 0.f, 0.f);
        const float* Vb4 = g_V + h * HDm + dq * 4;
        for (int nb = 0; nb < degPad; nb += 4) {
            int j = jlist[nb + ng];
            float e = sc_s[h][nb + ng];
            float4 v4 = *(const float4*)(Vb4 + (size_t)j * DD);
            acc4.x = fmaf(e, v4.x, acc4.x);
            acc4.y = fmaf(e, v4.y, acc4.y);
            acc4.z = fmaf(e, v4.z, acc4.z);
            acc4.w = fmaf(e, v4.w, acc4.w);
        }
#pragma unroll
        for (int o = 8; o <= 16; o <<= 1) {
            acc4.x += __shfl_xor_sync(0xffffffffu, acc4.x, o);
            acc4.y += __shfl_xor_sync(0xffffffffu, acc4.y, o);
            acc4.z += __shfl_xor_sync(0xffffffffu, acc4.z, o);
            acc4.w += __shfl_xor_sync(0xffffffffu, acc4.w, o);
        }
        if (ng == 0) {
            float inv = 1.f / lsum;
            float o0 = acc4.x * inv, o1 = acc4.y * inv;
            float o2 = acc4.z * inv, o3 = acc4.w * inv;
            int oidx = i * DD + h * HDm + dq * 4;
            uint2 ph, pl;
            ph.x = pack_hi(o0, o1); ph.y = pack_hi(o2, o3);
            pl.x = pack_lo(o0, o1); pl.y = pack_lo(o2, o3);
            *(uint2*)&g_attH[oidx] = ph;
            *(uint2*)&g_attL[oidx] = pl;
        }
    } else {
        const float* Vb = g_V + h * HDm + lane;
        float m = -1e30f, l = 0.f, accA = 0.f, accB = 0.f;
        for (int base = 0; base < deg; base += 8) {
            int j = jlist[base + b];
            const float4* kr = (const float4*)(g_K + (size_t)j * DD + h * HDm + dg * 8);
            float4 k0 = kr[0], k1 = kr[1];
            float s = q0.x * k0.x + q0.y * k0.y + q0.z * k0.z + q0.w * k0.w
                    + q1.x * k1.x + q1.y * k1.y + q1.z * k1.z + q1.w * k1.w;
            s += __shfl_xor_sync(0xffffffffu, s, 1);
            s += __shfl_xor_sync(0xffffffffu, s, 2);
            s *= scale;
            int ei = eidx[base + b];
            if (ei >= 0) s += g_ebias[ei * HH + h];
            if (base + b >= deg) s = -1e30f;
            float bm = s;
            bm = fmaxf(bm, __shfl_xor_sync(0xffffffffu, bm, 4));
            bm = fmaxf(bm, __shfl_xor_sync(0xffffffffu, bm, 8));
            bm = fmaxf(bm, __shfl_xor_sync(0xffffffffu, bm, 16));
            float nm = fmaxf(m, bm);
            float e = __expf(s - nm);
            float le = e;
            le += __shfl_xor_sync(0xffffffffu, le, 4);
            le += __shfl_xor_sync(0xffffffffu, le, 8);
            le += __shfl_xor_sync(0xffffffffu, le, 16);
            float sc = __expf(m - nm);
            l = l * sc + le;
            accA *= sc; accB *= sc;
            m = nm;
#pragma unroll
            for (int nb = 0; nb < 8; nb += 2) {
                float e0 = __shfl_sync(0xffffffffu, e, nb * 4);
                float e1 = __shfl_sync(0xffffffffu, e, nb * 4 + 4);
                int j0 = jlist[base + nb], j1 = jlist[base + nb + 1];
                accA = fmaf(e0, Vb[(size_t)j0 * DD], accA);
                accB = fmaf(e1, Vb[(size_t)j1 * DD], accB);
            }
        }
        float outv = (accA + accB) / l;
        __nv_bfloat16 hi = __float2bfloat16(outv);
        int oidx = i * DD + h * HDm + lane;
        g_attH[oidx] = hi;
        g_attL[oidx] = __float2bfloat16(outv - __bfloat162float(hi));
    }
}

// -------- fused slice-sum + residual + bias + LayerNorm, optional bf16 pair out --------
__global__ void add_ln_kernel(const float* __restrict__ x, int nslices,
                              const float* __restrict__ res, const float* __restrict__ eb,
                              const float* __restrict__ w, const float* __restrict__ b,
                              float* __restrict__ out,
                              __nv_bfloat16* __restrict__ outH, __nv_bfloat16* __restrict__ outL,
                              int writePair) {
    int i = blockIdx.x, t = threadIdx.x;
    float v = res[i * DD + t] + eb[t];
    for (int s = 0; s < nslices; s++) v += x[(size_t)s * NN * DD + i * DD + t];
    float a = v, a2 = v * v;
#pragma unroll
    for (int o = 16; o > 0; o >>= 1) {
        a += __shfl_xor_sync(0xffffffffu, a, o);
        a2 += __shfl_xor_sync(0xffffffffu, a2, o);
    }
    __shared__ float s1[8], s2[8];
    int warp = t >> 5, lane = t & 31;
    if (lane == 0) { s1[warp] = a; s2[warp] = a2; }
    __syncthreads();
    if (t < 32) {
        float x1 = (t < 8) ? s1[t] : 0.f;
        float x2 = (t < 8) ? s2[t] : 0.f;
#pragma unroll
        for (int o = 4; o > 0; o >>= 1) {
            x1 += __shfl_xor_sync(0xffffffffu, x1, o);
            x2 += __shfl_xor_sync(0xffffffffu, x2, o);
        }
        if (t == 0) { s1[0] = x1; s2[0] = x2; }
    }
    __syncthreads();
    float mu = s1[0] * (1.f / 256.f);
    float var = s2[0] * (1.f / 256.f) - mu * mu;
    float r = (v - mu) * rsqrtf(var + 1e-5f) * w[t] + b[t];
    out[i * DD + t] = r;
    if (writePair) {
        __nv_bfloat16 hi = __float2bfloat16(r);
        outH[i * DD + t] = hi;
        outL[i * DD + t] = __float2bfloat16(r - __bfloat162float(hi));
    }
}

// ---------------- launch ----------------
extern "C" void kernel_launch(void* const* d_in, const int* in_sizes, int n_in,
                              void* d_out, int out_size) {
    const float* node_feat = (const float*)d_in[0];
    const float* edge_feat = (const float*)d_in[1];
    const int*   src       = (const int*)d_in[2];
    const int*   dst       = (const int*)d_in[3];
    const float* Wq = (const float*)d_in[4];  const float* bq = (const float*)d_in[5];
    const float* Wk = (const float*)d_in[6];  const float* bk = (const float*)d_in[7];
    const float* Wv = (const float*)d_in[8];  const float* bv = (const float*)d_in[9];
    const float* Wo = (const float*)d_in[10]; const float* bo = (const float*)d_in[11];
    const float* We = (const float*)d_in[12]; const float* be = (const float*)d_in[13];
    const float* n1w = (const float*)d_in[14]; const float* n1b = (const float*)d_in[15];
    const float* W1 = (const float*)d_in[16]; const float* b1 = (const float*)d_in[17];
    const float* W2 = (const float*)d_in[18]; const float* b2 = (const float*)d_in[19];
    const float* n2w = (const float*)d_in[20]; const float* n2b = (const float*)d_in[21];
    float* out = (float*)d_out;

    float *Qp, *Kp, *Vp, *projp, *h1p, *f2p;
    cudaGetSymbolAddress((void**)&Qp, g_Q);
    cudaGetSymbolAddress((void**)&Kp, g_K);
    cudaGetSymbolAddress((void**)&Vp, g_V);
    cudaGetSymbolAddress((void**)&projp, g_proj);
    cudaGetSymbolAddress((void**)&h1p, g_h1);
    cudaGetSymbolAddress((void**)&f2p, g_f2);
    __nv_bfloat16 *nfH, *nfL, *WqH, *WqL, *WkH, *WkL, *WvH, *WvL, *WoH, *WoL,
                  *W1H, *W1L, *W2H, *W2L, *attH, *attL, *h1H, *h1L, *f1H, *f1L;
    cudaGetSymbolAddress((void**)&nfH, g_nfH);   cudaGetSymbolAddress((void**)&nfL, g_nfL);
    cudaGetSymbolAddress((void**)&WqH, g_WqH);   cudaGetSymbolAddress((void**)&WqL, g_WqL);
    cudaGetSymbolAddress((void**)&WkH, g_WkH);   cudaGetSymbolAddress((void**)&WkL, g_WkL);
    cudaGetSymbolAddress((void**)&WvH, g_WvH);   cudaGetSymbolAddress((void**)&WvL, g_WvL);
    cudaGetSymbolAddress((void**)&WoH, g_WoH);   cudaGetSymbolAddress((void**)&WoL, g_WoL);
    cudaGetSymbolAddress((void**)&W1H, g_W1H);   cudaGetSymbolAddress((void**)&W1L, g_W1L);
    cudaGetSymbolAddress((void**)&W2H, g_W2H);   cudaGetSymbolAddress((void**)&W2L, g_W2L);
    cudaGetSymbolAddress((void**)&attH, g_attH); cudaGetSymbolAddress((void**)&attL, g_attL);
    cudaGetSymbolAddress((void**)&h1H, g_h1H);   cudaGetSymbolAddress((void**)&h1L, g_h1L);
    cudaGetSymbolAddress((void**)&f1H, g_f1H);   cudaGetSymbolAddress((void**)&f1L, g_f1L);

    prep_scatter_kernel<<<5120, 256>>>(node_feat, Wq, Wk, Wv, Wo, W1, W2,
                                       src, dst, edge_feat, We, be);

    // QKV fused (z = weight select). grid (4,32,3)=384
    gemm_tc<<<dim3(DD / 64, NN / 64, 3), 128>>>(
        nfH, nfL, WqH, WkH, WvH, WqL, WkL, WvL, bq, bk, bv,
        Qp, Kp, Vp, nullptr, nullptr, DD, DD, 8);

    attn_kernel<<<NN, 256>>>();

    // Wo: split-K=4 into slice buffers. grid (4,32,4)=512
    gemm_tc<<<dim3(DD / 64, NN / 64, 4), 128>>>(
        attH, attL, WoH, WoH, WoH, WoL, WoL, WoL, bo, bo, bo,
        projp, nullptr, nullptr, nullptr, nullptr, DD, DD, 2);

    add_ln_kernel<<<NN, 256>>>(projp, 4, node_feat, bo, n1w, n1b, h1p, h1H, h1L, 1);

    // FFN1: bias+relu, bf16 pair out. grid (16,32)=512
    gemm_tc<<<dim3(DFF / 64, NN / 64, 1), 128>>>(
        h1H, h1L, W1H, W1H, W1H, W1L, W1L, W1L, b1, b1, b1,
        nullptr, nullptr, nullptr, f1H, f1L, DD, DFF, 1 | 4);

    // FFN2: split-K=4 into slice buffers. grid (4,32,4)=512
    gemm_tc<<<dim3(DD / 64, NN / 64, 4), 128>>>(
        f1H, f1L, W2H, W2H, W2H, W2L, W2L, W2L, b2, b2, b2,
        f2p, nullptr, nullptr, nullptr, nullptr, DFF, DD, 2);

    add_ln_kernel<<<NN, 256>>>(f2p, 4, h1p, b2, n2w, n2b, out, nullptr, nullptr, 0);
}

// round 15
// speedup vs baseline: 1.0280x; 1.0280x over previous
#include <cuda_runtime.h>
#include <cuda_bf16.h>
#include <math.h>
#include <stdint.h>

#define NN 2048
#define EE 32768
#define DD 256
#define HH 8
#define HDm 32
#define DFF 1024
#define MAXD 512

// ---------------- scratch (device globals; zero-initialized at load) ----------------
__device__ float    g_Q[NN * DD];
__device__ float    g_K[NN * DD];
__device__ float    g_V[NN * DD];
__device__ float    g_proj[4 * NN * DD];     // Wo split-K slices
__device__ float    g_h1[NN * DD];
__device__ float    g_f2[4 * NN * DD];       // FFN2 split-K slices
__device__ float    g_ebias[EE * HH];
__device__ unsigned g_adj[NN * NN / 32];
__device__ unsigned g_hasb[NN * NN / 32];
__device__ int      g_bidx[NN * NN];

// bf16 hi/lo pairs (pre-split fp32)
__device__ __nv_bfloat16 g_nfH[NN * DD],  g_nfL[NN * DD];
__device__ __nv_bfloat16 g_WqH[DD * DD],  g_WqL[DD * DD];
__device__ __nv_bfloat16 g_WkH[DD * DD],  g_WkL[DD * DD];
__device__ __nv_bfloat16 g_WvH[DD * DD],  g_WvL[DD * DD];
__device__ __nv_bfloat16 g_WoH[DD * DD],  g_WoL[DD * DD];
__device__ __nv_bfloat16 g_W1H[DD * DFF], g_W1L[DD * DFF];
__device__ __nv_bfloat16 g_W2H[DFF * DD], g_W2L[DFF * DD];
__device__ __nv_bfloat16 g_attH[NN * DD], g_attL[NN * DD];
__device__ __nv_bfloat16 g_h1H[NN * DD],  g_h1L[NN * DD];
__device__ __nv_bfloat16 g_f1H[NN * DFF], g_f1L[NN * DFF];

// ---------------- helpers ----------------
__device__ __forceinline__ uint32_t smem_u32(const void* p) {
    uint32_t a;
    asm("{ .reg .u64 t; cvta.to.shared.u64 t, %1; cvt.u32.u64 %0, t; }" : "=r"(a) : "l"(p));
    return a;
}
__device__ __forceinline__ void mma_bf16(float* d, const uint32_t* a, const uint32_t* b) {
    asm volatile(
        "mma.sync.aligned.m16n8k16.row.col.f32.bf16.bf16.f32 "
        "{%0,%1,%2,%3}, {%4,%5,%6,%7}, {%8,%9}, {%0,%1,%2,%3};"
        : "+f"(d[0]), "+f"(d[1]), "+f"(d[2]), "+f"(d[3])
        : "r"(a[0]), "r"(a[1]), "r"(a[2]), "r"(a[3]), "r"(b[0]), "r"(b[1]));
}
#define LDSM4(d0, d1, d2, d3, a) \
    asm volatile("ldmatrix.sync.aligned.m8n8.x4.shared.b16 {%0,%1,%2,%3},[%4];" \
        : "=r"(d0), "=r"(d1), "=r"(d2), "=r"(d3) : "r"(a))
#define LDSM4T(d0, d1, d2, d3, a) \
    asm volatile("ldmatrix.sync.aligned.m8n8.x4.trans.shared.b16 {%0,%1,%2,%3},[%4];" \
        : "=r"(d0), "=r"(d1), "=r"(d2), "=r"(d3) : "r"(a))

__device__ __forceinline__ uint32_t pack_hi(float f0, float f1) {
    __nv_bfloat16 h0 = __float2bfloat16(f0), h1 = __float2bfloat16(f1);
    return (uint32_t)__bfloat16_as_ushort(h0) | ((uint32_t)__bfloat16_as_ushort(h1) << 16);
}
__device__ __forceinline__ uint32_t pack_lo(float f0, float f1) {
    __nv_bfloat16 h0 = __float2bfloat16(f0), h1 = __float2bfloat16(f1);
    __nv_bfloat16 l0 = __float2bfloat16(f0 - __bfloat162float(h0));
    __nv_bfloat16 l1 = __float2bfloat16(f1 - __bfloat162float(h1));
    return (uint32_t)__bfloat16_as_ushort(l0) | ((uint32_t)__bfloat16_as_ushort(l1) << 16);
}

// ================= GEMM: 64x64 tile, BK=32, 4 warps, ldmatrix, double-buffered =================
// flags: 1=RELU, 2=SPLITK (slice -> C + z*NN*N, no bias), 4=OUT_PAIR, 8=z selects weight set
#define ASTR 40
#define BSTR 72
#define ABUF (64 * ASTR)
#define BBUF (32 * BSTR)

__global__ void __launch_bounds__(128) gemm_tc(
    const __nv_bfloat16* __restrict__ AH, const __nv_bfloat16* __restrict__ AL,
    const __nv_bfloat16* __restrict__ BH0, const __nv_bfloat16* __restrict__ BH1, const __nv_bfloat16* __restrict__ BH2,
    const __nv_bfloat16* __restrict__ BL0, const __nv_bfloat16* __restrict__ BL1, const __nv_bfloat16* __restrict__ BL2,
    const float* __restrict__ bias0, const float* __restrict__ bias1, const float* __restrict__ bias2,
    float* __restrict__ C0, float* __restrict__ C1, float* __restrict__ C2,
    __nv_bfloat16* __restrict__ CH, __nv_bfloat16* __restrict__ CL,
    int K, int N, int flags)
{
    __shared__ __align__(16) __nv_bfloat16 AsH[2][ABUF];
    __shared__ __align__(16) __nv_bfloat16 AsL[2][ABUF];
    __shared__ __align__(16) __nv_bfloat16 BsH[2][BBUF];
    __shared__ __align__(16) __nv_bfloat16 BsL[2][BBUF];

    const __nv_bfloat16* BH = BH0; const __nv_bfloat16* BL = BL0;
    const float* bias = bias0; float* C = C0;
    int kslice = 0, nsl = 1;
    if (flags & 8) {
        if (blockIdx.z == 1) { BH = BH1; BL = BL1; bias = bias1; C = C1; }
        else if (blockIdx.z == 2) { BH = BH2; BL = BL2; bias = bias2; C = C2; }
    } else if (flags & 2) {
        kslice = blockIdx.z; nsl = gridDim.z;
        C = C0 + (size_t)kslice * NN * N;
    }

    const int tid = threadIdx.x;
    const int lane = tid & 31;
    const int wid = tid >> 5;
    const int wm = wid >> 1, wn = wid & 1;
    const int g = lane >> 2, tg = lane & 3;
    const int m0 = blockIdx.y * 64;
    const int n0 = blockIdx.x * 64;

    const int nk = (K >> 5) / nsl;
    const int kstart = kslice * nk;

    float acc[2][4][4];
#pragma unroll
    for (int i = 0; i < 2; i++)
#pragma unroll
        for (int j = 0; j < 4; j++)
#pragma unroll
            for (int c = 0; c < 4; c++) acc[i][j][c] = 0.f;

    const uint32_t aOff = (((wm * 32 + (lane & 15)) * ASTR + ((lane >> 4) << 3)) << 1);
    const uint32_t bOff = ((((lane & 15)) * BSTR + wn * 32 + ((lane >> 4) << 3)) << 1);
    const uint32_t aBaseH0 = smem_u32(AsH[0]) + aOff;
    const uint32_t aBaseL0 = smem_u32(AsL[0]) + aOff;
    const uint32_t bBaseH0 = smem_u32(BsH[0]) + bOff;
    const uint32_t bBaseL0 = smem_u32(BsL[0]) + bOff;

    uint2 rAH[4], rAL[4], rBH[4], rBL[4];

#define LOADC(KC) do { \
    _Pragma("unroll") \
    for (int it = 0; it < 4; it++) { \
        int flat = tid * 4 + it * 512; \
        int r = flat >> 5, c = flat & 31; \
        size_t gi = (size_t)(m0 + r) * K + (KC) * 32 + c; \
        rAH[it] = *(const uint2*)(AH + gi); \
        rAL[it] = *(const uint2*)(AL + gi); \
        int k = flat >> 6, n = flat & 63; \
        size_t gj = (size_t)((KC) * 32 + k) * N + n0 + n; \
        rBH[it] = *(const uint2*)(BH + gj); \
        rBL[it] = *(const uint2*)(BL + gj); \
    } } while (0)

    LOADC(kstart);

    int buf = 0;
    for (int kc = 0; kc < nk; kc++, buf ^= 1) {
#pragma unroll
        for (int it = 0; it < 4; it++) {
            int flat = tid * 4 + it * 512;
            int r = flat >> 5, c = flat & 31;
            *(uint2*)&AsH[buf][r * ASTR + c] = rAH[it];
            *(uint2*)&AsL[buf][r * ASTR + c] = rAL[it];
            int k = flat >> 6, n = flat & 63;
            *(uint2*)&BsH[buf][k * BSTR + n] = rBH[it];
            *(uint2*)&BsL[buf][k * BSTR + n] = rBL[it];
        }
        __syncthreads();
        if (kc + 1 < nk) LOADC(kstart + kc + 1);

        const uint32_t aH = aBaseH0 + buf * (ABUF * 2);
        const uint32_t aL = aBaseL0 + buf * (ABUF * 2);
        const uint32_t bH = bBaseH0 + buf * (BBUF * 2);
        const uint32_t bL = bBaseL0 + buf * (BBUF * 2);
#pragma unroll
        for (int kk = 0; kk < 2; kk++) {
            const int kb = kk * 16;
            uint32_t ah[2][4], al[2][4], bh[4][2], bl[4][2];
            LDSM4(ah[0][0], ah[0][1], ah[0][2], ah[0][3], aH + (kb << 1));
            LDSM4(ah[1][0], ah[1][1], ah[1][2], ah[1][3], aH + ((16 * ASTR + kb) << 1));
            LDSM4(al[0][0], al[0][1], al[0][2], al[0][3], aL + (kb << 1));
            LDSM4(al[1][0], al[1][1], al[1][2], al[1][3], aL + ((16 * ASTR + kb) << 1));
            LDSM4T(bh[0][0], bh[0][1], bh[1][0], bh[1][1], bH + ((kb * BSTR) << 1));
            LDSM4T(bh[2][0], bh[2][1], bh[3][0], bh[3][1], bH + ((kb * BSTR + 16) << 1));
            LDSM4T(bl[0][0], bl[0][1], bl[1][0], bl[1][1], bL + ((kb * BSTR) << 1));
            LDSM4T(bl[2][0], bl[2][1], bl[3][0], bl[3][1], bL + ((kb * BSTR + 16) << 1));
#pragma unroll
            for (int i = 0; i < 2; i++)
#pragma unroll
                for (int j = 0; j < 4; j++) mma_bf16(acc[i][j], ah[i], bh[j]);
#pragma unroll
            for (int i = 0; i < 2; i++)
#pragma unroll
                for (int j = 0; j < 4; j++) mma_bf16(acc[i][j], ah[i], bl[j]);
#pragma unroll
            for (int i = 0; i < 2; i++)
#pragma unroll
                for (int j = 0; j < 4; j++) mma_bf16(acc[i][j], al[i], bh[j]);
        }
    }

    // ---- epilogue ----
#pragma unroll
    for (int i = 0; i < 2; i++) {
        int row = m0 + wm * 32 + i * 16 + g;
#pragma unroll
        for (int j = 0; j < 4; j++) {
            int col = n0 + wn * 32 + j * 8 + tg * 2;
            float v0 = acc[i][j][0], v1 = acc[i][j][1], v2 = acc[i][j][2], v3 = acc[i][j][3];
            if (flags & 2) {
                *(float2*)(C + (size_t)row * N + col) = make_float2(v0, v1);
                *(float2*)(C + (size_t)(row + 8) * N + col) = make_float2(v2, v3);
            } else {
                float b0f = bias[col], b1f = bias[col + 1];
                v0 += b0f; v1 += b1f; v2 += b0f; v3 += b1f;
                if (flags & 1) {
                    v0 = fmaxf(v0, 0.f); v1 = fmaxf(v1, 0.f);
                    v2 = fmaxf(v2, 0.f); v3 = fmaxf(v3, 0.f);
                }
                if (flags & 4) {
                    *(uint32_t*)&CH[(size_t)row * N + col] = pack_hi(v0, v1);
                    *(uint32_t*)&CL[(size_t)row * N + col] = pack_lo(v0, v1);
                    *(uint32_t*)&CH[(size_t)(row + 8) * N + col] = pack_hi(v2, v3);
                    *(uint32_t*)&CL[(size_t)(row + 8) * N + col] = pack_lo(v2, v3);
                } else {
                    *(float2*)(C + (size_t)row * N + col) = make_float2(v0, v1);
                    *(float2*)(C + (size_t)(row + 8) * N + col) = make_float2(v2, v3);
                }
            }
        }
    }
}

// -------- merged prep (vectorized x4) + edge-bias + scatter (one launch) --------
__global__ void prep_scatter_kernel(
    const float* __restrict__ nf,
    const float* __restrict__ Wq, const float* __restrict__ Wk,
    const float* __restrict__ Wv, const float* __restrict__ Wo,
    const float* __restrict__ W1, const float* __restrict__ W2,
    const int* __restrict__ src, const int* __restrict__ dst,
    const float* __restrict__ ef,
    const float* __restrict__ We, const float* __restrict__ be)
{
    int t = blockIdx.x * 256 + threadIdx.x;

    // ---- scatter part (first EE+NN threads; idempotent writes) ----
    if (t < EE) {
        const float* row = ef + t * 10;
        float r[10];
#pragma unroll
        for (int k = 0; k < 10; k++) r[k] = row[k];
#pragma unroll
        for (int h = 0; h < HH; h++) {
            float s = be[h];
#pragma unroll
            for (int k = 0; k < 10; k++) s = fmaf(r[k], We[k * HH + h], s);
            g_ebias[t * HH + h] = s;
        }
        int s = src[t], d = dst[t];
        int p1 = s * NN + d;
        int p2 = d * NN + s;
        atomicOr(&g_adj[p1 >> 5], 1u << (p1 & 31));
        atomicOr(&g_adj[p2 >> 5], 1u << (p2 & 31));
        atomicOr(&g_hasb[p1 >> 5], 1u << (p1 & 31));
        atomicMax(&g_bidx[p1], t);
    } else if (t < EE + NN) {
        int i = t - EE;
        int p = i * NN + i;
        atomicOr(&g_adj[p >> 5], 1u << (p & 31));
    }

    // ---- prep part: 4 elements per thread (all sizes divisible by 4) ----
    int q = t * 4;
    const float* s; __nv_bfloat16 *dh, *dl; int off;
    if      (q <  524288) { s = nf; dh = g_nfH; dl = g_nfL; off = q; }
    else if (q <  589824) { s = Wq; dh = g_WqH; dl = g_WqL; off = q - 524288; }
    else if (q <  655360) { s = Wk; dh = g_WkH; dl = g_WkL; off = q - 589824; }
    else if (q <  720896) { s = Wv; dh = g_WvH; dl = g_WvL; off = q - 655360; }
    else if (q <  786432) { s = Wo; dh = g_WoH; dl = g_WoL; off = q - 720896; }
    else if (q < 1048576) { s = W1; dh = g_W1H; dl = g_W1L; off = q - 786432; }
    else if (q < 1310720) { s = W2; dh = g_W2H; dl = g_W2L; off = q - 1048576; }
    else return;
    float4 v = *(const float4*)(s + off);
    uint2 ph, pl;
    ph.x = pack_hi(v.x, v.y); ph.y = pack_hi(v.z, v.w);
    pl.x = pack_lo(v.x, v.y); pl.y = pack_lo(v.z, v.w);
    *(uint2*)(dh + off) = ph;
    *(uint2*)(dl + off) = pl;
}

// ------- sparse attention: three-pass softmax; Pass C vectorized (float4 V) -------
__global__ void __launch_bounds__(256) attn_kernel() {
    const int i = blockIdx.x;
    const int tid = threadIdx.x;
    const int lane = tid & 31;
    const int h = tid >> 5;
    const int b = lane >> 2;
    const int dg = lane & 3;
    const int ng = lane >> 3;
    const int dq = lane & 7;

    __shared__ unsigned adjw[64];
    __shared__ int wbase[64];
    __shared__ int s_deg;
    __shared__ short jlist[2048 + 8];
    __shared__ short eidx[2048 + 8];
    __shared__ __align__(16) float qs[DD];
    __shared__ float sc_s[HH][MAXD];

    if (tid < 64) adjw[tid] = g_adj[i * 64 + tid];
    qs[tid] = g_Q[i * DD + tid];
    __syncthreads();

    if (tid < 32) {
        int c0 = __popc(adjw[2 * tid]), c1 = __popc(adjw[2 * tid + 1]);
        int s = c0 + c1, scan = s;
#pragma unroll
        for (int o = 1; o < 32; o <<= 1) {
            int v = __shfl_up_sync(0xffffffffu, scan, o);
            if (tid >= o) scan += v;
        }
        int excl = scan - s;
        wbase[2 * tid] = excl;
        wbase[2 * tid + 1] = excl + c0;
        if (tid == 31) s_deg = scan;
    }
    __syncthreads();
    if (tid < 64) {
        unsigned w = adjw[tid];
        int off = wbase[tid];
        while (w) {
            int bb = __ffs(w) - 1; w &= w - 1;
            int j = tid * 32 + bb;
            jlist[off] = (short)j;
            int p = i * NN + j;
            eidx[off] = ((g_hasb[p >> 5] >> (p & 31)) & 1u) ? (short)g_bidx[p] : (short)-1;
            off++;
        }
    }
    __syncthreads();
    const int deg = s_deg;
    if (tid < 8) { jlist[deg + tid] = jlist[0]; eidx[deg + tid] = -1; }
    __syncthreads();

    const float scale = 0.17677669529663687f;
    const float4* q4 = (const float4*)(qs + h * HDm + dg * 8);
    const float4 q0 = q4[0], q1 = q4[1];

    if (deg <= MAXD) {
        float mlane = -1e30f;
        for (int base = 0; base < deg; base += 8) {
            int j = jlist[base + b];
            const float4* kr = (const float4*)(g_K + (size_t)j * DD + h * HDm + dg * 8);
            float4 k0 = kr[0], k1 = kr[1];
            float s = q0.x * k0.x + q0.y * k0.y + q0.z * k0.z + q0.w * k0.w
                    + q1.x * k1.x + q1.y * k1.y + q1.z * k1.z + q1.w * k1.w;
            s += __shfl_xor_sync(0xffffffffu, s, 1);
            s += __shfl_xor_sync(0xffffffffu, s, 2);
            s *= scale;
            int ei = eidx[base + b];
            if (ei >= 0) s += g_ebias[ei * HH + h];
            if (base + b >= deg) s = -1e30f;
            mlane = fmaxf(mlane, s);
            if (dg == 0) sc_s[h][base + b] = s;
        }
#pragma unroll
        for (int o = 16; o > 0; o >>= 1)
            mlane = fmaxf(mlane, __shfl_xor_sync(0xffffffffu, mlane, o));
        const float m = mlane;

        const int degPad = (deg + 7) & ~7;
        float lsum = 0.f;
        for (int base = 0; base < degPad; base += 32) {
            int idx = base + lane;
            if (idx < degPad) {
                float e = (idx < deg) ? __expf(sc_s[h][idx] - m) : 0.f;
                sc_s[h][idx] = e;
                lsum += e;
            }
        }
#pragma unroll
        for (int o = 16; o > 0; o >>= 1) lsum += __shfl_xor_sync(0xffffffffu, lsum, o);

        float4 acc4 = make_float4(0.f, 0.f, 0.f, 0.f);
        const float* Vb4 = g_V + h * HDm + dq * 4;
        for (int nb = 0; nb < degPad; nb += 4) {
            int j = jlist[nb + ng];
            float e = sc_s[h][nb + ng];
            float4 v4 = *(const float4*)(Vb4 + (size_t)j * DD);
            acc4.x = fmaf(e, v4.x, acc4.x);
            acc4.y = fmaf(e, v4.y, acc4.y);
            acc4.z = fmaf(e, v4.z, acc4.z);
            acc4.w = fmaf(e, v4.w, acc4.w);
        }
#pragma unroll
        for (int o = 8; o <= 16; o <<= 1) {
            acc4.x += __shfl_xor_sync(0xffffffffu, acc4.x, o);
            acc4.y += __shfl_xor_sync(0xffffffffu, acc4.y, o);
            acc4.z += __shfl_xor_sync(0xffffffffu, acc4.z, o);
            acc4.w += __shfl_xor_sync(0xffffffffu, acc4.w, o);
        }
        if (ng == 0) {
            float inv = 1.f / lsum;
            float o0 = acc4.x * inv, o1 = acc4.y * inv;
            float o2 = acc4.z * inv, o3 = acc4.w * inv;
            int oidx = i * DD + h * HDm + dq * 4;
            uint2 ph, pl;
            ph.x = pack_hi(o0, o1); ph.y = pack_hi(o2, o3);
            pl.x = pack_lo(o0, o1); pl.y = pack_lo(o2, o3);
            *(uint2*)&g_attH[oidx] = ph;
            *(uint2*)&g_attL[oidx] = pl;
        }
    } else {
        const float* Vb = g_V + h * HDm + lane;
        float m = -1e30f, l = 0.f, accA = 0.f, accB = 0.f;
        for (int base = 0; base < deg; base += 8) {
            int j = jlist[base + b];
            const float4* kr = (const float4*)(g_K + (size_t)j * DD + h * HDm + dg * 8);
            float4 k0 = kr[0], k1 = kr[1];
            float s = q0.x * k0.x + q0.y * k0.y + q0.z * k0.z + q0.w * k0.w
                    + q1.x * k1.x + q1.y * k1.y + q1.z * k1.z + q1.w * k1.w;
            s += __shfl_xor_sync(0xffffffffu, s, 1);
            s += __shfl_xor_sync(0xffffffffu, s, 2);
            s *= scale;
            int ei = eidx[base + b];
            if (ei >= 0) s += g_ebias[ei * HH + h];
            if (base + b >= deg) s = -1e30f;
            float bm = s;
            bm = fmaxf(bm, __shfl_xor_sync(0xffffffffu, bm, 4));
            bm = fmaxf(bm, __shfl_xor_sync(0xffffffffu, bm, 8));
            bm = fmaxf(bm, __shfl_xor_sync(0xffffffffu, bm, 16));
            float nm = fmaxf(m, bm);
            float e = __expf(s - nm);
            float le = e;
            le += __shfl_xor_sync(0xffffffffu, le, 4);
            le += __shfl_xor_sync(0xffffffffu, le, 8);
            le += __shfl_xor_sync(0xffffffffu, le, 16);
            float sc = __expf(m - nm);
            l = l * sc + le;
            accA *= sc; accB *= sc;
            m = nm;
#pragma unroll
            for (int nb = 0; nb < 8; nb += 2) {
                float e0 = __shfl_sync(0xffffffffu, e, nb * 4);
                float e1 = __shfl_sync(0xffffffffu, e, nb * 4 + 4);
                int j0 = jlist[base + nb], j1 = jlist[base + nb + 1];
                accA = fmaf(e0, Vb[(size_t)j0 * DD], accA);
                accB = fmaf(e1, Vb[(size_t)j1 * DD], accB);
            }
        }
        float outv = (accA + accB) / l;
        __nv_bfloat16 hi = __float2bfloat16(outv);
        int oidx = i * DD + h * HDm + lane;
        g_attH[oidx] = hi;
        g_attL[oidx] = __float2bfloat16(outv - __bfloat162float(hi));
    }
}

// -------- fused slice-sum + residual + bias + LayerNorm, optional bf16 pair out --------
__global__ void add_ln_kernel(const float* __restrict__ x, int nslices,
                              const float* __restrict__ res, const float* __restrict__ eb,
                              const float* __restrict__ w, const float* __restrict__ b,
                              float* __restrict__ out,
                              __nv_bfloat16* __restrict__ outH, __nv_bfloat16* __restrict__ outL,
                              int writePair) {
    int i = blockIdx.x, t = threadIdx.x;
    float v = res[i * DD + t] + eb[t];
    for (int s = 0; s < nslices; s++) v += x[(size_t)s * NN * DD + i * DD + t];
    float a = v, a2 = v * v;
#pragma unroll
    for (int o = 16; o > 0; o >>= 1) {
        a += __shfl_xor_sync(0xffffffffu, a, o);
        a2 += __shfl_xor_sync(0xffffffffu, a2, o);
    }
    __shared__ float s1[8], s2[8];
    int warp = t >> 5, lane = t & 31;
    if (lane == 0) { s1[warp] = a; s2[warp] = a2; }
    __syncthreads();
    if (t < 32) {
        float x1 = (t < 8) ? s1[t] : 0.f;
        float x2 = (t < 8) ? s2[t] : 0.f;
#pragma unroll
        for (int o = 4; o > 0; o >>= 1) {
            x1 += __shfl_xor_sync(0xffffffffu, x1, o);
            x2 += __shfl_xor_sync(0xffffffffu, x2, o);
        }
        if (t == 0) { s1[0] = x1; s2[0] = x2; }
    }
    __syncthreads();
    float mu = s1[0] * (1.f / 256.f);
    float var = s2[0] * (1.f / 256.f) - mu * mu;
    float r = (v - mu) * rsqrtf(var + 1e-5f) * w[t] + b[t];
    out[i * DD + t] = r;
    if (writePair) {
        __nv_bfloat16 hi = __float2bfloat16(r);
        outH[i * DD + t] = hi;
        outL[i * DD + t] = __float2bfloat16(r - __bfloat162float(hi));
    }
}

// ---------------- launch ----------------
extern "C" void kernel_launch(void* const* d_in, const int* in_sizes, int n_in,
                              void* d_out, int out_size) {
    const float* node_feat = (const float*)d_in[0];
    const float* edge_feat = (const float*)d_in[1];
    const int*   src       = (const int*)d_in[2];
    const int*   dst       = (const int*)d_in[3];
    const float* Wq = (const float*)d_in[4];  const float* bq = (const float*)d_in[5];
    const float* Wk = (const float*)d_in[6];  const float* bk = (const float*)d_in[7];
    const float* Wv = (const float*)d_in[8];  const float* bv = (const float*)d_in[9];
    const float* Wo = (const float*)d_in[10]; const float* bo = (const float*)d_in[11];
    const float* We = (const float*)d_in[12]; const float* be = (const float*)d_in[13];
    const float* n1w = (const float*)d_in[14]; const float* n1b = (const float*)d_in[15];
    const float* W1 = (const float*)d_in[16]; const float* b1 = (const float*)d_in[17];
    const float* W2 = (const float*)d_in[18]; const float* b2 = (const float*)d_in[19];
    const float* n2w = (const float*)d_in[20]; const float* n2b = (const float*)d_in[21];
    float* out = (float*)d_out;

    float *Qp, *Kp, *Vp, *projp, *h1p, *f2p;
    cudaGetSymbolAddress((void**)&Qp, g_Q);
    cudaGetSymbolAddress((void**)&Kp, g_K);
    cudaGetSymbolAddress((void**)&Vp, g_V);
    cudaGetSymbolAddress((void**)&projp, g_proj);
    cudaGetSymbolAddress((void**)&h1p, g_h1);
    cudaGetSymbolAddress((void**)&f2p, g_f2);
    __nv_bfloat16 *nfH, *nfL, *WqH, *WqL, *WkH, *WkL, *WvH, *WvL, *WoH, *WoL,
                  *W1H, *W1L, *W2H, *W2L, *attH, *attL, *h1H, *h1L, *f1H, *f1L;
    cudaGetSymbolAddress((void**)&nfH, g_nfH);   cudaGetSymbolAddress((void**)&nfL, g_nfL);
    cudaGetSymbolAddress((void**)&WqH, g_WqH);   cudaGetSymbolAddress((void**)&WqL, g_WqL);
    cudaGetSymbolAddress((void**)&WkH, g_WkH);   cudaGetSymbolAddress((void**)&WkL, g_WkL);
    cudaGetSymbolAddress((void**)&WvH, g_WvH);   cudaGetSymbolAddress((void**)&WvL, g_WvL);
    cudaGetSymbolAddress((void**)&WoH, g_WoH);   cudaGetSymbolAddress((void**)&WoL, g_WoL);
    cudaGetSymbolAddress((void**)&W1H, g_W1H);   cudaGetSymbolAddress((void**)&W1L, g_W1L);
    cudaGetSymbolAddress((void**)&W2H, g_W2H);   cudaGetSymbolAddress((void**)&W2L, g_W2L);
    cudaGetSymbolAddress((void**)&attH, g_attH); cudaGetSymbolAddress((void**)&attL, g_attL);
    cudaGetSymbolAddress((void**)&h1H, g_h1H);   cudaGetSymbolAddress((void**)&h1L, g_h1L);
    cudaGetSymbolAddress((void**)&f1H, g_f1H);   cudaGetSymbolAddress((void**)&f1L, g_f1L);

    // merged prep (x4 vectorized) + scatter: 327680 prep threads, 1280 blocks
    prep_scatter_kernel<<<1280, 256>>>(node_feat, Wq, Wk, Wv, Wo, W1, W2,
                                       src, dst, edge_feat, We, be);

    // QKV fused (z = weight select). grid (4,32,3)=384
    gemm_tc<<<dim3(DD / 64, NN / 64, 3), 128>>>(
        nfH, nfL, WqH, WkH, WvH, WqL, WkL, WvL, bq, bk, bv,
        Qp, Kp, Vp, nullptr, nullptr, DD, DD, 8);

    attn_kernel<<<NN, 256>>>();

    // Wo: split-K=4 into slice buffers. grid (4,32,4)=512
    gemm_tc<<<dim3(DD / 64, NN / 64, 4), 128>>>(
        attH, attL, WoH, WoH, WoH, WoL, WoL, WoL, bo, bo, bo,
        projp, nullptr, nullptr, nullptr, nullptr, DD, DD, 2);

    add_ln_kernel<<<NN, 256>>>(projp, 4, node_feat, bo, n1w, n1b, h1p, h1H, h1L, 1);

    // FFN1: bias+relu, bf16 pair out. grid (16,32)=512
    gemm_tc<<<dim3(DFF / 64, NN / 64, 1), 128>>>(
        h1H, h1L, W1H, W1H, W1H, W1L, W1L, W1L, b1, b1, b1,
        nullptr, nullptr, nullptr, f1H, f1L, DD, DFF, 1 | 4);

    // FFN2: split-K=4 into slice buffers. grid (4,32,4)=512
    gemm_tc<<<dim3(DD / 64, NN / 64, 4), 128>>>(
        f1H, f1L, W2H, W2H, W2H, W2L, W2L, W2L, b2, b2, b2,
        f2p, nullptr, nullptr, nullptr, nullptr, DFF, DD, 2);

    add_ln_kernel<<<NN, 256>>>(f2p, 4, h1p, b2, n2w, n2b, out, nullptr, nullptr, 0);
}

// round 16
// speedup vs baseline: 1.0313x; 1.0033x over previous
#include <cuda_runtime.h>
#include <cuda_bf16.h>
#include <math.h>
#include <stdint.h>

#define NN 2048
#define EE 32768
#define DD 256
#define HH 8
#define HDm 32
#define DFF 1024
#define MAXD 512

// ---------------- scratch (device globals; zero-initialized at load) ----------------
__device__ float    g_Q[NN * DD];
__device__ float    g_K[NN * DD];
__device__ float    g_V[NN * DD];
__device__ float    g_proj[2 * NN * DD];     // Wo split-K slices
__device__ float    g_h1[NN * DD];
__device__ float    g_f2[2 * NN * DD];       // FFN2 split-K slices
__device__ float    g_ebias[EE * HH];
__device__ unsigned g_adj[NN * NN / 32];
__device__ unsigned g_hasb[NN * NN / 32];
__device__ int      g_bidx[NN * NN];

// bf16 hi/lo pairs (pre-split fp32)
__device__ __nv_bfloat16 g_nfH[NN * DD],  g_nfL[NN * DD];
__device__ __nv_bfloat16 g_WqH[DD * DD],  g_WqL[DD * DD];
__device__ __nv_bfloat16 g_WkH[DD * DD],  g_WkL[DD * DD];
__device__ __nv_bfloat16 g_WvH[DD * DD],  g_WvL[DD * DD];
__device__ __nv_bfloat16 g_WoH[DD * DD],  g_WoL[DD * DD];
__device__ __nv_bfloat16 g_W1H[DD * DFF], g_W1L[DD * DFF];
__device__ __nv_bfloat16 g_W2H[DFF * DD], g_W2L[DFF * DD];
__device__ __nv_bfloat16 g_attH[NN * DD], g_attL[NN * DD];
__device__ __nv_bfloat16 g_h1H[NN * DD],  g_h1L[NN * DD];
__device__ __nv_bfloat16 g_f1H[NN * DFF], g_f1L[NN * DFF];

// ---------------- helpers ----------------
__device__ __forceinline__ uint32_t smem_u32(const void* p) {
    uint32_t a;
    asm("{ .reg .u64 t; cvta.to.shared.u64 t, %1; cvt.u32.u64 %0, t; }" : "=r"(a) : "l"(p));
    return a;
}
__device__ __forceinline__ void mma_bf16(float* d, const uint32_t* a, const uint32_t* b) {
    asm volatile(
        "mma.sync.aligned.m16n8k16.row.col.f32.bf16.bf16.f32 "
        "{%0,%1,%2,%3}, {%4,%5,%6,%7}, {%8,%9}, {%0,%1,%2,%3};"
        : "+f"(d[0]), "+f"(d[1]), "+f"(d[2]), "+f"(d[3])
        : "r"(a[0]), "r"(a[1]), "r"(a[2]), "r"(a[3]), "r"(b[0]), "r"(b[1]));
}
#define LDSM4(d0, d1, d2, d3, a) \
    asm volatile("ldmatrix.sync.aligned.m8n8.x4.shared.b16 {%0,%1,%2,%3},[%4];" \
        : "=r"(d0), "=r"(d1), "=r"(d2), "=r"(d3) : "r"(a))
#define LDSM4T(d0, d1, d2, d3, a) \
    asm volatile("ldmatrix.sync.aligned.m8n8.x4.trans.shared.b16 {%0,%1,%2,%3},[%4];" \
        : "=r"(d0), "=r"(d1), "=r"(d2), "=r"(d3) : "r"(a))

__device__ __forceinline__ uint32_t pack_hi(float f0, float f1) {
    __nv_bfloat16 h0 = __float2bfloat16(f0), h1 = __float2bfloat16(f1);
    return (uint32_t)__bfloat16_as_ushort(h0) | ((uint32_t)__bfloat16_as_ushort(h1) << 16);
}
__device__ __forceinline__ uint32_t pack_lo(float f0, float f1) {
    __nv_bfloat16 h0 = __float2bfloat16(f0), h1 = __float2bfloat16(f1);
    __nv_bfloat16 l0 = __float2bfloat16(f0 - __bfloat162float(h0));
    __nv_bfloat16 l1 = __float2bfloat16(f1 - __bfloat162float(h1));
    return (uint32_t)__bfloat16_as_ushort(l0) | ((uint32_t)__bfloat16_as_ushort(l1) << 16);
}

// ================= GEMM: 64x64 tile, BK=32, 4 warps, ldmatrix, double-buffered =================
// flags: 1=RELU, 2=SPLITK (slice -> C + z*NN*N, no bias), 4=OUT_PAIR, 8=z selects weight set
#define ASTR 40
#define BSTR 72
#define ABUF (64 * ASTR)
#define BBUF (32 * BSTR)

__global__ void __launch_bounds__(128) gemm_tc(
    const __nv_bfloat16* __restrict__ AH, const __nv_bfloat16* __restrict__ AL,
    const __nv_bfloat16* __restrict__ BH0, const __nv_bfloat16* __restrict__ BH1, const __nv_bfloat16* __restrict__ BH2,
    const __nv_bfloat16* __restrict__ BL0, const __nv_bfloat16* __restrict__ BL1, const __nv_bfloat16* __restrict__ BL2,
    const float* __restrict__ bias0, const float* __restrict__ bias1, const float* __restrict__ bias2,
    float* __restrict__ C0, float* __restrict__ C1, float* __restrict__ C2,
    __nv_bfloat16* __restrict__ CH, __nv_bfloat16* __restrict__ CL,
    int K, int N, int flags)
{
    __shared__ __align__(16) __nv_bfloat16 AsH[2][ABUF];
    __shared__ __align__(16) __nv_bfloat16 AsL[2][ABUF];
    __shared__ __align__(16) __nv_bfloat16 BsH[2][BBUF];
    __shared__ __align__(16) __nv_bfloat16 BsL[2][BBUF];

    const __nv_bfloat16* BH = BH0; const __nv_bfloat16* BL = BL0;
    const float* bias = bias0; float* C = C0;
    int kslice = 0, nsl = 1;
    if (flags & 8) {
        if (blockIdx.z == 1) { BH = BH1; BL = BL1; bias = bias1; C = C1; }
        else if (blockIdx.z == 2) { BH = BH2; BL = BL2; bias = bias2; C = C2; }
    } else if (flags & 2) {
        kslice = blockIdx.z; nsl = gridDim.z;
        C = C0 + (size_t)kslice * NN * N;
    }

    const int tid = threadIdx.x;
    const int lane = tid & 31;
    const int wid = tid >> 5;
    const int wm = wid >> 1, wn = wid & 1;
    const int g = lane >> 2, tg = lane & 3;
    const int m0 = blockIdx.y * 64;
    const int n0 = blockIdx.x * 64;

    const int nk = (K >> 5) / nsl;
    const int kstart = kslice * nk;

    float acc[2][4][4];
#pragma unroll
    for (int i = 0; i < 2; i++)
#pragma unroll
        for (int j = 0; j < 4; j++)
#pragma unroll
            for (int c = 0; c < 4; c++) acc[i][j][c] = 0.f;

    const uint32_t aOff = (((wm * 32 + (lane & 15)) * ASTR + ((lane >> 4) << 3)) << 1);
    const uint32_t bOff = ((((lane & 15)) * BSTR + wn * 32 + ((lane >> 4) << 3)) << 1);
    const uint32_t aBaseH0 = smem_u32(AsH[0]) + aOff;
    const uint32_t aBaseL0 = smem_u32(AsL[0]) + aOff;
    const uint32_t bBaseH0 = smem_u32(BsH[0]) + bOff;
    const uint32_t bBaseL0 = smem_u32(BsL[0]) + bOff;

    uint2 rAH[4], rAL[4], rBH[4], rBL[4];

#define LOADC(KC) do { \
    _Pragma("unroll") \
    for (int it = 0; it < 4; it++) { \
        int flat = tid * 4 + it * 512; \
        int r = flat >> 5, c = flat & 31; \
        size_t gi = (size_t)(m0 + r) * K + (KC) * 32 + c; \
        rAH[it] = *(const uint2*)(AH + gi); \
        rAL[it] = *(const uint2*)(AL + gi); \
        int k = flat >> 6, n = flat & 63; \
        size_t gj = (size_t)((KC) * 32 + k) * N + n0 + n; \
        rBH[it] = *(const uint2*)(BH + gj); \
        rBL[it] = *(const uint2*)(BL + gj); \
    } } while (0)

    LOADC(kstart);

    int buf = 0;
    for (int kc = 0; kc < nk; kc++, buf ^= 1) {
#pragma unroll
        for (int it = 0; it < 4; it++) {
            int flat = tid * 4 + it * 512;
            int r = flat >> 5, c = flat & 31;
            *(uint2*)&AsH[buf][r * ASTR + c] = rAH[it];
            *(uint2*)&AsL[buf][r * ASTR + c] = rAL[it];
            int k = flat >> 6, n = flat & 63;
            *(uint2*)&BsH[buf][k * BSTR + n] = rBH[it];
            *(uint2*)&BsL[buf][k * BSTR + n] = rBL[it];
        }
        __syncthreads();
        if (kc + 1 < nk) LOADC(kstart + kc + 1);

        const uint32_t aH = aBaseH0 + buf * (ABUF * 2);
        const uint32_t aL = aBaseL0 + buf * (ABUF * 2);
        const uint32_t bH = bBaseH0 + buf * (BBUF * 2);
        const uint32_t bL = bBaseL0 + buf * (BBUF * 2);
#pragma unroll
        for (int kk = 0; kk < 2; kk++) {
            const int kb = kk * 16;
            uint32_t ah[2][4], al[2][4], bh[4][2], bl[4][2];
            LDSM4(ah[0][0], ah[0][1], ah[0][2], ah[0][3], aH + (kb << 1));
            LDSM4(ah[1][0], ah[1][1], ah[1][2], ah[1][3], aH + ((16 * ASTR + kb) << 1));
            LDSM4(al[0][0], al[0][1], al[0][2], al[0][3], aL + (kb << 1));
            LDSM4(al[1][0], al[1][1], al[1][2], al[1][3], aL + ((16 * ASTR + kb) << 1));
            LDSM4T(bh[0][0], bh[0][1], bh[1][0], bh[1][1], bH + ((kb * BSTR) << 1));
            LDSM4T(bh[2][0], bh[2][1], bh[3][0], bh[3][1], bH + ((kb * BSTR + 16) << 1));
            LDSM4T(bl[0][0], bl[0][1], bl[1][0], bl[1][1], bL + ((kb * BSTR) << 1));
            LDSM4T(bl[2][0], bl[2][1], bl[3][0], bl[3][1], bL + ((kb * BSTR + 16) << 1));
#pragma unroll
            for (int i = 0; i < 2; i++)
#pragma unroll
                for (int j = 0; j < 4; j++) mma_bf16(acc[i][j], ah[i], bh[j]);
#pragma unroll
            for (int i = 0; i < 2; i++)
#pragma unroll
                for (int j = 0; j < 4; j++) mma_bf16(acc[i][j], ah[i], bl[j]);
#pragma unroll
            for (int i = 0; i < 2; i++)
#pragma unroll
                for (int j = 0; j < 4; j++) mma_bf16(acc[i][j], al[i], bh[j]);
        }
    }

    // ---- epilogue ----
#pragma unroll
    for (int i = 0; i < 2; i++) {
        int row = m0 + wm * 32 + i * 16 + g;
#pragma unroll
        for (int j = 0; j < 4; j++) {
            int col = n0 + wn * 32 + j * 8 + tg * 2;
            float v0 = acc[i][j][0], v1 = acc[i][j][1], v2 = acc[i][j][2], v3 = acc[i][j][3];
            if (flags & 2) {
                *(float2*)(C + (size_t)row * N + col) = make_float2(v0, v1);
                *(float2*)(C + (size_t)(row + 8) * N + col) = make_float2(v2, v3);
            } else {
                float b0f = bias[col], b1f = bias[col + 1];
                v0 += b0f; v1 += b1f; v2 += b0f; v3 += b1f;
                if (flags & 1) {
                    v0 = fmaxf(v0, 0.f); v1 = fmaxf(v1, 0.f);
                    v2 = fmaxf(v2, 0.f); v3 = fmaxf(v3, 0.f);
                }
                if (flags & 4) {
                    *(uint32_t*)&CH[(size_t)row * N + col] = pack_hi(v0, v1);
                    *(uint32_t*)&CL[(size_t)row * N + col] = pack_lo(v0, v1);
                    *(uint32_t*)&CH[(size_t)(row + 8) * N + col] = pack_hi(v2, v3);
                    *(uint32_t*)&CL[(size_t)(row + 8) * N + col] = pack_lo(v2, v3);
                } else {
                    *(float2*)(C + (size_t)row * N + col) = make_float2(v0, v1);
                    *(float2*)(C + (size_t)(row + 8) * N + col) = make_float2(v2, v3);
                }
            }
        }
    }
}

// -------- merged prep (vectorized x4) + edge-bias + scatter (one launch) --------
__global__ void prep_scatter_kernel(
    const float* __restrict__ nf,
    const float* __restrict__ Wq, const float* __restrict__ Wk,
    const float* __restrict__ Wv, const float* __restrict__ Wo,
    const float* __restrict__ W1, const float* __restrict__ W2,
    const int* __restrict__ src, const int* __restrict__ dst,
    const float* __restrict__ ef,
    const float* __restrict__ We, const float* __restrict__ be)
{
    int t = blockIdx.x * 256 + threadIdx.x;

    if (t < EE) {
        const float* row = ef + t * 10;
        float r[10];
#pragma unroll
        for (int k = 0; k < 10; k++) r[k] = row[k];
#pragma unroll
        for (int h = 0; h < HH; h++) {
            float s = be[h];
#pragma unroll
            for (int k = 0; k < 10; k++) s = fmaf(r[k], We[k * HH + h], s);
            g_ebias[t * HH + h] = s;
        }
        int s = src[t], d = dst[t];
        int p1 = s * NN + d;
        int p2 = d * NN + s;
        atomicOr(&g_adj[p1 >> 5], 1u << (p1 & 31));
        atomicOr(&g_adj[p2 >> 5], 1u << (p2 & 31));
        atomicOr(&g_hasb[p1 >> 5], 1u << (p1 & 31));
        atomicMax(&g_bidx[p1], t);
    } else if (t < EE + NN) {
        int i = t - EE;
        int p = i * NN + i;
        atomicOr(&g_adj[p >> 5], 1u << (p & 31));
    }

    int q = t * 4;
    const float* s; __nv_bfloat16 *dh, *dl; int off;
    if      (q <  524288) { s = nf; dh = g_nfH; dl = g_nfL; off = q; }
    else if (q <  589824) { s = Wq; dh = g_WqH; dl = g_WqL; off = q - 524288; }
    else if (q <  655360) { s = Wk; dh = g_WkH; dl = g_WkL; off = q - 589824; }
    else if (q <  720896) { s = Wv; dh = g_WvH; dl = g_WvL; off = q - 655360; }
    else if (q <  786432) { s = Wo; dh = g_WoH; dl = g_WoL; off = q - 720896; }
    else if (q < 1048576) { s = W1; dh = g_W1H; dl = g_W1L; off = q - 786432; }
    else if (q < 1310720) { s = W2; dh = g_W2H; dl = g_W2L; off = q - 1048576; }
    else return;
    float4 v = *(const float4*)(s + off);
    uint2 ph, pl;
    ph.x = pack_hi(v.x, v.y); ph.y = pack_hi(v.z, v.w);
    pl.x = pack_lo(v.x, v.y); pl.y = pack_lo(v.z, v.w);
    *(uint2*)(dh + off) = ph;
    *(uint2*)(dl + off) = pl;
}

// ------- sparse attention: three-pass softmax; Pass C vectorized (float4 V) -------
__global__ void __launch_bounds__(256) attn_kernel() {
    const int i = blockIdx.x;
    const int tid = threadIdx.x;
    const int lane = tid & 31;
    const int h = tid >> 5;
    const int b = lane >> 2;
    const int dg = lane & 3;
    const int ng = lane >> 3;
    const int dq = lane & 7;

    __shared__ unsigned adjw[64];
    __shared__ int wbase[64];
    __shared__ int s_deg;
    __shared__ short jlist[2048 + 8];
    __shared__ short eidx[2048 + 8];
    __shared__ __align__(16) float qs[DD];
    __shared__ float sc_s[HH][MAXD];

    if (tid < 64) adjw[tid] = g_adj[i * 64 + tid];
    qs[tid] = g_Q[i * DD + tid];
    __syncthreads();

    if (tid < 32) {
        int c0 = __popc(adjw[2 * tid]), c1 = __popc(adjw[2 * tid + 1]);
        int s = c0 + c1, scan = s;
#pragma unroll
        for (int o = 1; o < 32; o <<= 1) {
            int v = __shfl_up_sync(0xffffffffu, scan, o);
            if (tid >= o) scan += v;
        }
        int excl = scan - s;
        wbase[2 * tid] = excl;
        wbase[2 * tid + 1] = excl + c0;
        if (tid == 31) s_deg = scan;
    }
    __syncthreads();
    if (tid < 64) {
        unsigned w = adjw[tid];
        int off = wbase[tid];
        while (w) {
            int bb = __ffs(w) - 1; w &= w - 1;
            int j = tid * 32 + bb;
            jlist[off] = (short)j;
            int p = i * NN + j;
            eidx[off] = ((g_hasb[p >> 5] >> (p & 31)) & 1u) ? (short)g_bidx[p] : (short)-1;
            off++;
        }
    }
    __syncthreads();
    const int deg = s_deg;
    if (tid < 8) { jlist[deg + tid] = jlist[0]; eidx[deg + tid] = -1; }
    __syncthreads();

    const float scale = 0.17677669529663687f;
    const float4* q4 = (const float4*)(qs + h * HDm + dg * 8);
    const float4 q0 = q4[0], q1 = q4[1];

    if (deg <= MAXD) {
        float mlane = -1e30f;
        for (int base = 0; base < deg; base += 8) {
            int j = jlist[base + b];
            const float4* kr = (const float4*)(g_K + (size_t)j * DD + h * HDm + dg * 8);
            float4 k0 = kr[0], k1 = kr[1];
            float s = q0.x * k0.x + q0.y * k0.y + q0.z * k0.z + q0.w * k0.w
                    + q1.x * k1.x + q1.y * k1.y + q1.z * k1.z + q1.w * k1.w;
            s += __shfl_xor_sync(0xffffffffu, s, 1);
            s += __shfl_xor_sync(0xffffffffu, s, 2);
            s *= scale;
            int ei = eidx[base + b];
            if (ei >= 0) s += g_ebias[ei * HH + h];
            if (base + b >= deg) s = -1e30f;
            mlane = fmaxf(mlane, s);
            if (dg == 0) sc_s[h][base + b] = s;
        }
#pragma unroll
        for (int o = 16; o > 0; o >>= 1)
            mlane = fmaxf(mlane, __shfl_xor_sync(0xffffffffu, mlane, o));
        const float m = mlane;

        const int degPad = (deg + 7) & ~7;
        float lsum = 0.f;
        for (int base = 0; base < degPad; base += 32) {
            int idx = base + lane;
            if (idx < degPad) {
                float e = (idx < deg) ? __expf(sc_s[h][idx] - m) : 0.f;
                sc_s[h][idx] = e;
                lsum += e;
            }
        }
#pragma unroll
        for (int o = 16; o > 0; o >>= 1) lsum += __shfl_xor_sync(0xffffffffu, lsum, o);

        float4 acc4 = make_float4(0.f, 0.f, 0.f, 0.f);
        const float* Vb4 = g_V + h * HDm + dq * 4;
        for (int nb = 0; nb < degPad; nb += 4) {
            int j = jlist[nb + ng];
            float e = sc_s[h][nb + ng];
            float4 v4 = *(const float4*)(Vb4 + (size_t)j * DD);
            acc4.x = fmaf(e, v4.x, acc4.x);
            acc4.y = fmaf(e, v4.y, acc4.y);
            acc4.z = fmaf(e, v4.z, acc4.z);
            acc4.w = fmaf(e, v4.w, acc4.w);
        }
#pragma unroll
        for (int o = 8; o <= 16; o <<= 1) {
            acc4.x += __shfl_xor_sync(0xffffffffu, acc4.x, o);
            acc4.y += __shfl_xor_sync(0xffffffffu, acc4.y, o);
            acc4.z += __shfl_xor_sync(0xffffffffu, acc4.z, o);
            acc4.w += __shfl_xor_sync(0xffffffffu, acc4.w, o);
        }
        if (ng == 0) {
            float inv = 1.f / lsum;
            float o0 = acc4.x * inv, o1 = acc4.y * inv;
            float o2 = acc4.z * inv, o3 = acc4.w * inv;
            int oidx = i * DD + h * HDm + dq * 4;
            uint2 ph, pl;
            ph.x = pack_hi(o0, o1); ph.y = pack_hi(o2, o3);
            pl.x = pack_lo(o0, o1); pl.y = pack_lo(o2, o3);
            *(uint2*)&g_attH[oidx] = ph;
            *(uint2*)&g_attL[oidx] = pl;
        }
    } else {
        const float* Vb = g_V + h * HDm + lane;
        float m = -1e30f, l = 0.f, accA = 0.f, accB = 0.f;
        for (int base = 0; base < deg; base += 8) {
            int j = jlist[base + b];
            const float4* kr = (const float4*)(g_K + (size_t)j * DD + h * HDm + dg * 8);
            float4 k0 = kr[0], k1 = kr[1];
            float s = q0.x * k0.x + q0.y * k0.y + q0.z * k0.z + q0.w * k0.w
                    + q1.x * k1.x + q1.y * k1.y + q1.z * k1.z + q1.w * k1.w;
            s += __shfl_xor_sync(0xffffffffu, s, 1);
            s += __shfl_xor_sync(0xffffffffu, s, 2);
            s *= scale;
            int ei = eidx[base + b];
            if (ei >= 0) s += g_ebias[ei * HH + h];
            if (base + b >= deg) s = -1e30f;
            float bm = s;
            bm = fmaxf(bm, __shfl_xor_sync(0xffffffffu, bm, 4));
            bm = fmaxf(bm, __shfl_xor_sync(0xffffffffu, bm, 8));
            bm = fmaxf(bm, __shfl_xor_sync(0xffffffffu, bm, 16));
            float nm = fmaxf(m, bm);
            float e = __expf(s - nm);
            float le = e;
            le += __shfl_xor_sync(0xffffffffu, le, 4);
            le += __shfl_xor_sync(0xffffffffu, le, 8);
            le += __shfl_xor_sync(0xffffffffu, le, 16);
            float sc = __expf(m - nm);
            l = l * sc + le;
            accA *= sc; accB *= sc;
            m = nm;
#pragma unroll
            for (int nb = 0; nb < 8; nb += 2) {
                float e0 = __shfl_sync(0xffffffffu, e, nb * 4);
                float e1 = __shfl_sync(0xffffffffu, e, nb * 4 + 4);
                int j0 = jlist[base + nb], j1 = jlist[base + nb + 1];
                accA = fmaf(e0, Vb[(size_t)j0 * DD], accA);
                accB = fmaf(e1, Vb[(size_t)j1 * DD], accB);
            }
        }
        float outv = (accA + accB) / l;
        __nv_bfloat16 hi = __float2bfloat16(outv);
        int oidx = i * DD + h * HDm + lane;
        g_attH[oidx] = hi;
        g_attL[oidx] = __float2bfloat16(outv - __bfloat162float(hi));
    }
}

// -------- fused slice-sum + residual + bias + LayerNorm, optional bf16 pair out --------
__global__ void add_ln_kernel(const float* __restrict__ x, int nslices,
                              const float* __restrict__ res, const float* __restrict__ eb,
                              const float* __restrict__ w, const float* __restrict__ b,
                              float* __restrict__ out,
                              __nv_bfloat16* __restrict__ outH, __nv_bfloat16* __restrict__ outL,
                              int writePair) {
    int i = blockIdx.x, t = threadIdx.x;
    float v = res[i * DD + t] + eb[t];
    for (int s = 0; s < nslices; s++) v += x[(size_t)s * NN * DD + i * DD + t];
    float a = v, a2 = v * v;
#pragma unroll
    for (int o = 16; o > 0; o >>= 1) {
        a += __shfl_xor_sync(0xffffffffu, a, o);
        a2 += __shfl_xor_sync(0xffffffffu, a2, o);
    }
    __shared__ float s1[8], s2[8];
    int warp = t >> 5, lane = t & 31;
    if (lane == 0) { s1[warp] = a; s2[warp] = a2; }
    __syncthreads();
    if (t < 32) {
        float x1 = (t < 8) ? s1[t] : 0.f;
        float x2 = (t < 8) ? s2[t] : 0.f;
#pragma unroll
        for (int o = 4; o > 0; o >>= 1) {
            x1 += __shfl_xor_sync(0xffffffffu, x1, o);
            x2 += __shfl_xor_sync(0xffffffffu, x2, o);
        }
        if (t == 0) { s1[0] = x1; s2[0] = x2; }
    }
    __syncthreads();
    float mu = s1[0] * (1.f / 256.f);
    float var = s2[0] * (1.f / 256.f) - mu * mu;
    float r = (v - mu) * rsqrtf(var + 1e-5f) * w[t] + b[t];
    out[i * DD + t] = r;
    if (writePair) {
        __nv_bfloat16 hi = __float2bfloat16(r);
        outH[i * DD + t] = hi;
        outL[i * DD + t] = __float2bfloat16(r - __bfloat162float(hi));
    }
}

// ---------------- launch ----------------
extern "C" void kernel_launch(void* const* d_in, const int* in_sizes, int n_in,
                              void* d_out, int out_size) {
    const float* node_feat = (const float*)d_in[0];
    const float* edge_feat = (const float*)d_in[1];
    const int*   src       = (const int*)d_in[2];
    const int*   dst       = (const int*)d_in[3];
    const float* Wq = (const float*)d_in[4];  const float* bq = (const float*)d_in[5];
    const float* Wk = (const float*)d_in[6];  const float* bk = (const float*)d_in[7];
    const float* Wv = (const float*)d_in[8];  const float* bv = (const float*)d_in[9];
    const float* Wo = (const float*)d_in[10]; const float* bo = (const float*)d_in[11];
    const float* We = (const float*)d_in[12]; const float* be = (const float*)d_in[13];
    const float* n1w = (const float*)d_in[14]; const float* n1b = (const float*)d_in[15];
    const float* W1 = (const float*)d_in[16]; const float* b1 = (const float*)d_in[17];
    const float* W2 = (const float*)d_in[18]; const float* b2 = (const float*)d_in[19];
    const float* n2w = (const float*)d_in[20]; const float* n2b = (const float*)d_in[21];
    float* out = (float*)d_out;

    float *Qp, *Kp, *Vp, *projp, *h1p, *f2p;
    cudaGetSymbolAddress((void**)&Qp, g_Q);
    cudaGetSymbolAddress((void**)&Kp, g_K);
    cudaGetSymbolAddress((void**)&Vp, g_V);
    cudaGetSymbolAddress((void**)&projp, g_proj);
    cudaGetSymbolAddress((void**)&h1p, g_h1);
    cudaGetSymbolAddress((void**)&f2p, g_f2);
    __nv_bfloat16 *nfH, *nfL, *WqH, *WqL, *WkH, *WkL, *WvH, *WvL, *WoH, *WoL,
                  *W1H, *W1L, *W2H, *W2L, *attH, *attL, *h1H, *h1L, *f1H, *f1L;
    cudaGetSymbolAddress((void**)&nfH, g_nfH);   cudaGetSymbolAddress((void**)&nfL, g_nfL);
    cudaGetSymbolAddress((void**)&WqH, g_WqH);   cudaGetSymbolAddress((void**)&WqL, g_WqL);
    cudaGetSymbolAddress((void**)&WkH, g_WkH);   cudaGetSymbolAddress((void**)&WkL, g_WkL);
    cudaGetSymbolAddress((void**)&WvH, g_WvH);   cudaGetSymbolAddress((void**)&WvL, g_WvL);
    cudaGetSymbolAddress((void**)&WoH, g_WoH);   cudaGetSymbolAddress((void**)&WoL, g_WoL);
    cudaGetSymbolAddress((void**)&W1H, g_W1H);   cudaGetSymbolAddress((void**)&W1L, g_W1L);
    cudaGetSymbolAddress((void**)&W2H, g_W2H);   cudaGetSymbolAddress((void**)&W2L, g_W2L);
    cudaGetSymbolAddress((void**)&attH, g_attH); cudaGetSymbolAddress((void**)&attL, g_attL);
    cudaGetSymbolAddress((void**)&h1H, g_h1H);   cudaGetSymbolAddress((void**)&h1L, g_h1L);
    cudaGetSymbolAddress((void**)&f1H, g_f1H);   cudaGetSymbolAddress((void**)&f1L, g_f1L);

    // merged prep (x4 vectorized) + scatter
    prep_scatter_kernel<<<1280, 256>>>(node_feat, Wq, Wk, Wv, Wo, W1, W2,
                                       src, dst, edge_feat, We, be);

    // QKV fused (z = weight select). grid (4,32,3)=384
    gemm_tc<<<dim3(DD / 64, NN / 64, 3), 128>>>(
        nfH, nfL, WqH, WkH, WvH, WqL, WkL, WvL, bq, bk, bv,
        Qp, Kp, Vp, nullptr, nullptr, DD, DD, 8);

    attn_kernel<<<NN, 256>>>();

    // Wo: split-K=2 into slice buffers (R13 evidence: same GEMM time as split-4,
    // but halves add_ln slice traffic). grid (4,32,2)=256
    gemm_tc<<<dim3(DD / 64, NN / 64, 2), 128>>>(
        attH, attL, WoH, WoH, WoH, WoL, WoL, WoL, bo, bo, bo,
        projp, nullptr, nullptr, nullptr, nullptr, DD, DD, 2);

    add_ln_kernel<<<NN, 256>>>(projp, 2, node_feat, bo, n1w, n1b, h1p, h1H, h1L, 1);

    // FFN1: bias+relu, bf16 pair out. grid (16,32)=512
    gemm_tc<<<dim3(DFF / 64, NN / 64, 1), 128>>>(
        h1H, h1L, W1H, W1H, W1H, W1L, W1L, W1L, b1, b1, b1,
        nullptr, nullptr, nullptr, f1H, f1L, DD, DFF, 1 | 4);

    // FFN2: split-K=2 into slice buffers. grid (4,32,2)=256
    gemm_tc<<<dim3(DD / 64, NN / 64, 2), 128>>>(
        f1H, f1L, W2H, W2H, W2H, W2L, W2L, W2L, b2, b2, b2,
        f2p, nullptr, nullptr, nullptr, nullptr, DFF, DD, 2);

    add_ln_kernel<<<NN, 256>>>(f2p, 2, h1p, b2, n2w, n2b, out, nullptr, nullptr, 0);
}

// round 17
// speedup vs baseline: 1.0470x; 1.0152x over previous
#include <cuda_runtime.h>
#include <cuda_bf16.h>
#include <math.h>
#include <stdint.h>

#define NN 2048
#define EE 32768
#define DD 256
#define HH 8
#define HDm 32
#define DFF 1024
#define MAXD 512

// ---------------- scratch (device globals; zero-initialized at load) ----------------
__device__ float    g_Q[NN * DD];
__device__ float    g_K[NN * DD];
__device__ float    g_V[NN * DD];
__device__ float    g_proj[2 * NN * DD];     // Wo split-K slices
__device__ float    g_h1[NN * DD];
__device__ float    g_f2[2 * NN * DD];       // FFN2 split-K slices
__device__ float    g_ebias[EE * HH];
__device__ unsigned g_adj[NN * NN / 32];
__device__ unsigned g_hasb[NN * NN / 32];
__device__ int      g_bidx[NN * NN];

// bf16 hi/lo pairs (pre-split fp32)
__device__ __nv_bfloat16 g_nfH[NN * DD],  g_nfL[NN * DD];
__device__ __nv_bfloat16 g_WqH[DD * DD],  g_WqL[DD * DD];
__device__ __nv_bfloat16 g_WkH[DD * DD],  g_WkL[DD * DD];
__device__ __nv_bfloat16 g_WvH[DD * DD],  g_WvL[DD * DD];
__device__ __nv_bfloat16 g_WoH[DD * DD],  g_WoL[DD * DD];
__device__ __nv_bfloat16 g_W1H[DD * DFF], g_W1L[DD * DFF];
__device__ __nv_bfloat16 g_W2H[DFF * DD], g_W2L[DFF * DD];
__device__ __nv_bfloat16 g_attH[NN * DD], g_attL[NN * DD];
__device__ __nv_bfloat16 g_h1H[NN * DD],  g_h1L[NN * DD];
__device__ __nv_bfloat16 g_f1H[NN * DFF], g_f1L[NN * DFF];

// ---------------- helpers ----------------
__device__ __forceinline__ uint32_t smem_u32(const void* p) {
    uint32_t a;
    asm("{ .reg .u64 t; cvta.to.shared.u64 t, %1; cvt.u32.u64 %0, t; }" : "=r"(a) : "l"(p));
    return a;
}
__device__ __forceinline__ void mma_bf16(float* d, const uint32_t* a, const uint32_t* b) {
    asm volatile(
        "mma.sync.aligned.m16n8k16.row.col.f32.bf16.bf16.f32 "
        "{%0,%1,%2,%3}, {%4,%5,%6,%7}, {%8,%9}, {%0,%1,%2,%3};"
        : "+f"(d[0]), "+f"(d[1]), "+f"(d[2]), "+f"(d[3])
        : "r"(a[0]), "r"(a[1]), "r"(a[2]), "r"(a[3]), "r"(b[0]), "r"(b[1]));
}
#define LDSM4(d0, d1, d2, d3, a) \
    asm volatile("ldmatrix.sync.aligned.m8n8.x4.shared.b16 {%0,%1,%2,%3},[%4];" \
        : "=r"(d0), "=r"(d1), "=r"(d2), "=r"(d3) : "r"(a))
#define LDSM4T(d0, d1, d2, d3, a) \
    asm volatile("ldmatrix.sync.aligned.m8n8.x4.trans.shared.b16 {%0,%1,%2,%3},[%4];" \
        : "=r"(d0), "=r"(d1), "=r"(d2), "=r"(d3) : "r"(a))

__device__ __forceinline__ uint32_t pack_hi(float f0, float f1) {
    __nv_bfloat16 h0 = __float2bfloat16(f0), h1 = __float2bfloat16(f1);
    return (uint32_t)__bfloat16_as_ushort(h0) | ((uint32_t)__bfloat16_as_ushort(h1) << 16);
}
__device__ __forceinline__ uint32_t pack_lo(float f0, float f1) {
    __nv_bfloat16 h0 = __float2bfloat16(f0), h1 = __float2bfloat16(f1);
    __nv_bfloat16 l0 = __float2bfloat16(f0 - __bfloat162float(h0));
    __nv_bfloat16 l1 = __float2bfloat16(f1 - __bfloat162float(h1));
    return (uint32_t)__bfloat16_as_ushort(l0) | ((uint32_t)__bfloat16_as_ushort(l1) << 16);
}

// ================= GEMM: 64x64 tile, BK=32, 4 warps, ldmatrix, double-buffered =================
// flags: 1=RELU, 2=SPLITK (slice -> C + z*NN*N, no bias), 4=OUT_PAIR, 8=z selects weight set
#define ASTR 40
#define BSTR 72
#define ABUF (64 * ASTR)
#define BBUF (32 * BSTR)

__global__ void __launch_bounds__(128) gemm_tc(
    const __nv_bfloat16* __restrict__ AH, const __nv_bfloat16* __restrict__ AL,
    const __nv_bfloat16* __restrict__ BH0, const __nv_bfloat16* __restrict__ BH1, const __nv_bfloat16* __restrict__ BH2,
    const __nv_bfloat16* __restrict__ BL0, const __nv_bfloat16* __restrict__ BL1, const __nv_bfloat16* __restrict__ BL2,
    const float* __restrict__ bias0, const float* __restrict__ bias1, const float* __restrict__ bias2,
    float* __restrict__ C0, float* __restrict__ C1, float* __restrict__ C2,
    __nv_bfloat16* __restrict__ CH, __nv_bfloat16* __restrict__ CL,
    int K, int N, int flags)
{
    __shared__ __align__(16) __nv_bfloat16 AsH[2][ABUF];
    __shared__ __align__(16) __nv_bfloat16 AsL[2][ABUF];
    __shared__ __align__(16) __nv_bfloat16 BsH[2][BBUF];
    __shared__ __align__(16) __nv_bfloat16 BsL[2][BBUF];

    const __nv_bfloat16* BH = BH0; const __nv_bfloat16* BL = BL0;
    const float* bias = bias0; float* C = C0;
    int kslice = 0, nsl = 1;
    if (flags & 8) {
        if (blockIdx.z == 1) { BH = BH1; BL = BL1; bias = bias1; C = C1; }
        else if (blockIdx.z == 2) { BH = BH2; BL = BL2; bias = bias2; C = C2; }
    } else if (flags & 2) {
        kslice = blockIdx.z; nsl = gridDim.z;
        C = C0 + (size_t)kslice * NN * N;
    }

    const int tid = threadIdx.x;
    const int lane = tid & 31;
    const int wid = tid >> 5;
    const int wm = wid >> 1, wn = wid & 1;
    const int g = lane >> 2, tg = lane & 3;
    const int m0 = blockIdx.y * 64;
    const int n0 = blockIdx.x * 64;

    const int nk = (K >> 5) / nsl;
    const int kstart = kslice * nk;

    float acc[2][4][4];
#pragma unroll
    for (int i = 0; i < 2; i++)
#pragma unroll
        for (int j = 0; j < 4; j++)
#pragma unroll
            for (int c = 0; c < 4; c++) acc[i][j][c] = 0.f;

    const uint32_t aOff = (((wm * 32 + (lane & 15)) * ASTR + ((lane >> 4) << 3)) << 1);
    const uint32_t bOff = ((((lane & 15)) * BSTR + wn * 32 + ((lane >> 4) << 3)) << 1);
    const uint32_t aBaseH0 = smem_u32(AsH[0]) + aOff;
    const uint32_t aBaseL0 = smem_u32(AsL[0]) + aOff;
    const uint32_t bBaseH0 = smem_u32(BsH[0]) + bOff;
    const uint32_t bBaseL0 = smem_u32(BsL[0]) + bOff;

    uint2 rAH[4], rAL[4], rBH[4], rBL[4];

#define LOADC(KC) do { \
    _Pragma("unroll") \
    for (int it = 0; it < 4; it++) { \
        int flat = tid * 4 + it * 512; \
        int r = flat >> 5, c = flat & 31; \
        size_t gi = (size_t)(m0 + r) * K + (KC) * 32 + c; \
        rAH[it] = *(const uint2*)(AH + gi); \
        rAL[it] = *(const uint2*)(AL + gi); \
        int k = flat >> 6, n = flat & 63; \
        size_t gj = (size_t)((KC) * 32 + k) * N + n0 + n; \
        rBH[it] = *(const uint2*)(BH + gj); \
        rBL[it] = *(const uint2*)(BL + gj); \
    } } while (0)

    LOADC(kstart);

    int buf = 0;
    for (int kc = 0; kc < nk; kc++, buf ^= 1) {
#pragma unroll
        for (int it = 0; it < 4; it++) {
            int flat = tid * 4 + it * 512;
            int r = flat >> 5, c = flat & 31;
            *(uint2*)&AsH[buf][r * ASTR + c] = rAH[it];
            *(uint2*)&AsL[buf][r * ASTR + c] = rAL[it];
            int k = flat >> 6, n = flat & 63;
            *(uint2*)&BsH[buf][k * BSTR + n] = rBH[it];
            *(uint2*)&BsL[buf][k * BSTR + n] = rBL[it];
        }
        __syncthreads();
        if (kc + 1 < nk) LOADC(kstart + kc + 1);

        const uint32_t aH = aBaseH0 + buf * (ABUF * 2);
        const uint32_t aL = aBaseL0 + buf * (ABUF * 2);
        const uint32_t bH = bBaseH0 + buf * (BBUF * 2);
        const uint32_t bL = bBaseL0 + buf * (BBUF * 2);
#pragma unroll
        for (int kk = 0; kk < 2; kk++) {
            const int kb = kk * 16;
            uint32_t ah[2][4], al[2][4], bh[4][2], bl[4][2];
            LDSM4(ah[0][0], ah[0][1], ah[0][2], ah[0][3], aH + (kb << 1));
            LDSM4(ah[1][0], ah[1][1], ah[1][2], ah[1][3], aH + ((16 * ASTR + kb) << 1));
            LDSM4(al[0][0], al[0][1], al[0][2], al[0][3], aL + (kb << 1));
            LDSM4(al[1][0], al[1][1], al[1][2], al[1][3], aL + ((16 * ASTR + kb) << 1));
            LDSM4T(bh[0][0], bh[0][1], bh[1][0], bh[1][1], bH + ((kb * BSTR) << 1));
            LDSM4T(bh[2][0], bh[2][1], bh[3][0], bh[3][1], bH + ((kb * BSTR + 16) << 1));
            LDSM4T(bl[0][0], bl[0][1], bl[1][0], bl[1][1], bL + ((kb * BSTR) << 1));
            LDSM4T(bl[2][0], bl[2][1], bl[3][0], bl[3][1], bL + ((kb * BSTR + 16) << 1));
#pragma unroll
            for (int i = 0; i < 2; i++)
#pragma unroll
                for (int j = 0; j < 4; j++) mma_bf16(acc[i][j], ah[i], bh[j]);
#pragma unroll
            for (int i = 0; i < 2; i++)
#pragma unroll
                for (int j = 0; j < 4; j++) mma_bf16(acc[i][j], ah[i], bl[j]);
#pragma unroll
            for (int i = 0; i < 2; i++)
#pragma unroll
                for (int j = 0; j < 4; j++) mma_bf16(acc[i][j], al[i], bh[j]);
        }
    }

    // ---- epilogue ----
#pragma unroll
    for (int i = 0; i < 2; i++) {
        int row = m0 + wm * 32 + i * 16 + g;
#pragma unroll
        for (int j = 0; j < 4; j++) {
            int col = n0 + wn * 32 + j * 8 + tg * 2;
            float v0 = acc[i][j][0], v1 = acc[i][j][1], v2 = acc[i][j][2], v3 = acc[i][j][3];
            if (flags & 2) {
                *(float2*)(C + (size_t)row * N + col) = make_float2(v0, v1);
                *(float2*)(C + (size_t)(row + 8) * N + col) = make_float2(v2, v3);
            } else {
                float b0f = bias[col], b1f = bias[col + 1];
                v0 += b0f; v1 += b1f; v2 += b0f; v3 += b1f;
                if (flags & 1) {
                    v0 = fmaxf(v0, 0.f); v1 = fmaxf(v1, 0.f);
                    v2 = fmaxf(v2, 0.f); v3 = fmaxf(v3, 0.f);
                }
                if (flags & 4) {
                    *(uint32_t*)&CH[(size_t)row * N + col] = pack_hi(v0, v1);
                    *(uint32_t*)&CL[(size_t)row * N + col] = pack_lo(v0, v1);
                    *(uint32_t*)&CH[(size_t)(row + 8) * N + col] = pack_hi(v2, v3);
                    *(uint32_t*)&CL[(size_t)(row + 8) * N + col] = pack_lo(v2, v3);
                } else {
                    *(float2*)(C + (size_t)row * N + col) = make_float2(v0, v1);
                    *(float2*)(C + (size_t)(row + 8) * N + col) = make_float2(v2, v3);
                }
            }
        }
    }
}

// -------- merged prep (vectorized x4) + edge-bias + scatter (one launch) --------
__global__ void prep_scatter_kernel(
    const float* __restrict__ nf,
    const float* __restrict__ Wq, const float* __restrict__ Wk,
    const float* __restrict__ Wv, const float* __restrict__ Wo,
    const float* __restrict__ W1, const float* __restrict__ W2,
    const int* __restrict__ src, const int* __restrict__ dst,
    const float* __restrict__ ef,
    const float* __restrict__ We, const float* __restrict__ be)
{
    int t = blockIdx.x * 256 + threadIdx.x;

    if (t < EE) {
        const float* row = ef + t * 10;
        float r[10];
#pragma unroll
        for (int k = 0; k < 10; k++) r[k] = row[k];
#pragma unroll
        for (int h = 0; h < HH; h++) {
            float s = be[h];
#pragma unroll
            for (int k = 0; k < 10; k++) s = fmaf(r[k], We[k * HH + h], s);
            g_ebias[t * HH + h] = s;
        }
        int s = src[t], d = dst[t];
        int p1 = s * NN + d;
        int p2 = d * NN + s;
        atomicOr(&g_adj[p1 >> 5], 1u << (p1 & 31));
        atomicOr(&g_adj[p2 >> 5], 1u << (p2 & 31));
        atomicOr(&g_hasb[p1 >> 5], 1u << (p1 & 31));
        atomicMax(&g_bidx[p1], t);
    } else if (t < EE + NN) {
        int i = t - EE;
        int p = i * NN + i;
        atomicOr(&g_adj[p >> 5], 1u << (p & 31));
    }

    int q = t * 4;
    const float* s; __nv_bfloat16 *dh, *dl; int off;
    if      (q <  524288) { s = nf; dh = g_nfH; dl = g_nfL; off = q; }
    else if (q <  589824) { s = Wq; dh = g_WqH; dl = g_WqL; off = q - 524288; }
    else if (q <  655360) { s = Wk; dh = g_WkH; dl = g_WkL; off = q - 589824; }
    else if (q <  720896) { s = Wv; dh = g_WvH; dl = g_WvL; off = q - 655360; }
    else if (q <  786432) { s = Wo; dh = g_WoH; dl = g_WoL; off = q - 720896; }
    else if (q < 1048576) { s = W1; dh = g_W1H; dl = g_W1L; off = q - 786432; }
    else if (q < 1310720) { s = W2; dh = g_W2H; dl = g_W2L; off = q - 1048576; }
    else return;
    float4 v = *(const float4*)(s + off);
    uint2 ph, pl;
    ph.x = pack_hi(v.x, v.y); ph.y = pack_hi(v.z, v.w);
    pl.x = pack_lo(v.x, v.y); pl.y = pack_lo(v.z, v.w);
    *(uint2*)(dh + off) = ph;
    *(uint2*)(dl + off) = pl;
}

// ------- sparse attention: three-pass softmax; parallel eidx resolution -------
__global__ void __launch_bounds__(256) attn_kernel() {
    const int i = blockIdx.x;
    const int tid = threadIdx.x;
    const int lane = tid & 31;
    const int h = tid >> 5;
    const int b = lane >> 2;
    const int dg = lane & 3;
    const int ng = lane >> 3;
    const int dq = lane & 7;

    __shared__ unsigned adjw[64];
    __shared__ int wbase[64];
    __shared__ int s_deg;
    __shared__ short jlist[2048 + 8];
    __shared__ short eidx[2048 + 8];
    __shared__ __align__(16) float qs[DD];
    __shared__ float sc_s[HH][MAXD];

    if (tid < 64) adjw[tid] = g_adj[i * 64 + tid];
    qs[tid] = g_Q[i * DD + tid];
    __syncthreads();

    if (tid < 32) {
        int c0 = __popc(adjw[2 * tid]), c1 = __popc(adjw[2 * tid + 1]);
        int s = c0 + c1, scan = s;
#pragma unroll
        for (int o = 1; o < 32; o <<= 1) {
            int v = __shfl_up_sync(0xffffffffu, scan, o);
            if (tid >= o) scan += v;
        }
        int excl = scan - s;
        wbase[2 * tid] = excl;
        wbase[2 * tid + 1] = excl + c0;
        if (tid == 31) s_deg = scan;
    }
    __syncthreads();
    // expand bitmap -> jlist only (cheap, local)
    if (tid < 64) {
        unsigned w = adjw[tid];
        int off = wbase[tid];
        while (w) {
            int bb = __ffs(w) - 1; w &= w - 1;
            jlist[off++] = (short)(tid * 32 + bb);
        }
    }
    __syncthreads();
    const int deg = s_deg;
    // parallel eidx resolution: all 256 threads, 1 neighbor each (deg << 256)
    for (int idx = tid; idx < deg; idx += 256) {
        int j = jlist[idx];
        int p = i * NN + j;
        eidx[idx] = ((g_hasb[p >> 5] >> (p & 31)) & 1u) ? (short)g_bidx[p] : (short)-1;
    }
    if (tid < 8) { jlist[deg + tid] = jlist[0]; eidx[deg + tid] = -1; }
    __syncthreads();

    const float scale = 0.17677669529663687f;
    const float4* q4 = (const float4*)(qs + h * HDm + dg * 8);
    const float4 q0 = q4[0], q1 = q4[1];

    if (deg <= MAXD) {
        float mlane = -1e30f;
        for (int base = 0; base < deg; base += 8) {
            int j = jlist[base + b];
            const float4* kr = (const float4*)(g_K + (size_t)j * DD + h * HDm + dg * 8);
            float4 k0 = kr[0], k1 = kr[1];
            float s = q0.x * k0.x + q0.y * k0.y + q0.z * k0.z + q0.w * k0.w
                    + q1.x * k1.x + q1.y * k1.y + q1.z * k1.z + q1.w * k1.w;
            s += __shfl_xor_sync(0xffffffffu, s, 1);
            s += __shfl_xor_sync(0xffffffffu, s, 2);
            s *= scale;
            int ei = eidx[base + b];
            if (ei >= 0) s += g_ebias[ei * HH + h];
            if (base + b >= deg) s = -1e30f;
            mlane = fmaxf(mlane, s);
            if (dg == 0) sc_s[h][base + b] = s;
        }
#pragma unroll
        for (int o = 16; o > 0; o >>= 1)
            mlane = fmaxf(mlane, __shfl_xor_sync(0xffffffffu, mlane, o));
        const float m = mlane;

        const int degPad = (deg + 7) & ~7;
        float lsum = 0.f;
        for (int base = 0; base < degPad; base += 32) {
            int idx = base + lane;
            if (idx < degPad) {
                float e = (idx < deg) ? __expf(sc_s[h][idx] - m) : 0.f;
                sc_s[h][idx] = e;
                lsum += e;
            }
        }
#pragma unroll
        for (int o = 16; o > 0; o >>= 1) lsum += __shfl_xor_sync(0xffffffffu, lsum, o);

        float4 acc4 = make_float4(0.f, 0.f, 0.f, 0.f);
        const float* Vb4 = g_V + h * HDm + dq * 4;
        for (int nb = 0; nb < degPad; nb += 4) {
            int j = jlist[nb + ng];
            float e = sc_s[h][nb + ng];
            float4 v4 = *(const float4*)(Vb4 + (size_t)j * DD);
            acc4.x = fmaf(e, v4.x, acc4.x);
            acc4.y = fmaf(e, v4.y, acc4.y);
            acc4.z = fmaf(e, v4.z, acc4.z);
            acc4.w = fmaf(e, v4.w, acc4.w);
        }
#pragma unroll
        for (int o = 8; o <= 16; o <<= 1) {
            acc4.x += __shfl_xor_sync(0xffffffffu, acc4.x, o);
            acc4.y += __shfl_xor_sync(0xffffffffu, acc4.y, o);
            acc4.z += __shfl_xor_sync(0xffffffffu, acc4.z, o);
            acc4.w += __shfl_xor_sync(0xffffffffu, acc4.w, o);
        }
        if (ng == 0) {
            float inv = 1.f / lsum;
            float o0 = acc4.x * inv, o1 = acc4.y * inv;
            float o2 = acc4.z * inv, o3 = acc4.w * inv;
            int oidx = i * DD + h * HDm + dq * 4;
            uint2 ph, pl;
            ph.x = pack_hi(o0, o1); ph.y = pack_hi(o2, o3);
            pl.x = pack_lo(o0, o1); pl.y = pack_lo(o2, o3);
            *(uint2*)&g_attH[oidx] = ph;
            *(uint2*)&g_attL[oidx] = pl;
        }
    } else {
        const float* Vb = g_V + h * HDm + lane;
        float m = -1e30f, l = 0.f, accA = 0.f, accB = 0.f;
        for (int base = 0; base < deg; base += 8) {
            int j = jlist[base + b];
            const float4* kr = (const float4*)(g_K + (size_t)j * DD + h * HDm + dg * 8);
            float4 k0 = kr[0], k1 = kr[1];
            float s = q0.x * k0.x + q0.y * k0.y + q0.z * k0.z + q0.w * k0.w
                    + q1.x * k1.x + q1.y * k1.y + q1.z * k1.z + q1.w * k1.w;
            s += __shfl_xor_sync(0xffffffffu, s, 1);
            s += __shfl_xor_sync(0xffffffffu, s, 2);
            s *= scale;
            int ei = eidx[base + b];
            if (ei >= 0) s += g_ebias[ei * HH + h];
            if (base + b >= deg) s = -1e30f;
            float bm = s;
            bm = fmaxf(bm, __shfl_xor_sync(0xffffffffu, bm, 4));
            bm = fmaxf(bm, __shfl_xor_sync(0xffffffffu, bm, 8));
            bm = fmaxf(bm, __shfl_xor_sync(0xffffffffu, bm, 16));
            float nm = fmaxf(m, bm);
            float e = __expf(s - nm);
            float le = e;
            le += __shfl_xor_sync(0xffffffffu, le, 4);
            le += __shfl_xor_sync(0xffffffffu, le, 8);
            le += __shfl_xor_sync(0xffffffffu, le, 16);
            float sc = __expf(m - nm);
            l = l * sc + le;
            accA *= sc; accB *= sc;
            m = nm;
#pragma unroll
            for (int nb = 0; nb < 8; nb += 2) {
                float e0 = __shfl_sync(0xffffffffu, e, nb * 4);
                float e1 = __shfl_sync(0xffffffffu, e, nb * 4 + 4);
                int j0 = jlist[base + nb], j1 = jlist[base + nb + 1];
                accA = fmaf(e0, Vb[(size_t)j0 * DD], accA);
                accB = fmaf(e1, Vb[(size_t)j1 * DD], accB);
            }
        }
        float outv = (accA + accB) / l;
        __nv_bfloat16 hi = __float2bfloat16(outv);
        int oidx = i * DD + h * HDm + lane;
        g_attH[oidx] = hi;
        g_attL[oidx] = __float2bfloat16(outv - __bfloat162float(hi));
    }
}

// -------- fused slice-sum + residual + bias + LayerNorm, optional bf16 pair out --------
__global__ void add_ln_kernel(const float* __restrict__ x, int nslices,
                              const float* __restrict__ res, const float* __restrict__ eb,
                              const float* __restrict__ w, const float* __restrict__ b,
                              float* __restrict__ out,
                              __nv_bfloat16* __restrict__ outH, __nv_bfloat16* __restrict__ outL,
                              int writePair) {
    int i = blockIdx.x, t = threadIdx.x;
    float v = res[i * DD + t] + eb[t];
    for (int s = 0; s < nslices; s++) v += x[(size_t)s * NN * DD + i * DD + t];
    float a = v, a2 = v * v;
#pragma unroll
    for (int o = 16; o > 0; o >>= 1) {
        a += __shfl_xor_sync(0xffffffffu, a, o);
        a2 += __shfl_xor_sync(0xffffffffu, a2, o);
    }
    __shared__ float s1[8], s2[8];
    int warp = t >> 5, lane = t & 31;
    if (lane == 0) { s1[warp] = a; s2[warp] = a2; }
    __syncthreads();
    if (t < 32) {
        float x1 = (t < 8) ? s1[t] : 0.f;
        float x2 = (t < 8) ? s2[t] : 0.f;
#pragma unroll
        for (int o = 4; o > 0; o >>= 1) {
            x1 += __shfl_xor_sync(0xffffffffu, x1, o);
            x2 += __shfl_xor_sync(0xffffffffu, x2, o);
        }
        if (t == 0) { s1[0] = x1; s2[0] = x2; }
    }
    __syncthreads();
    float mu = s1[0] * (1.f / 256.f);
    float var = s2[0] * (1.f / 256.f) - mu * mu;
    float r = (v - mu) * rsqrtf(var + 1e-5f) * w[t] + b[t];
    out[i * DD + t] = r;
    if (writePair) {
        __nv_bfloat16 hi = __float2bfloat16(r);
        outH[i * DD + t] = hi;
        outL[i * DD + t] = __float2bfloat16(r - __bfloat162float(hi));
    }
}

// ---------------- launch ----------------
extern "C" void kernel_launch(void* const* d_in, const int* in_sizes, int n_in,
                              void* d_out, int out_size) {
    const float* node_feat = (const float*)d_in[0];
    const float* edge_feat = (const float*)d_in[1];
    const int*   src       = (const int*)d_in[2];
    const int*   dst       = (const int*)d_in[3];
    const float* Wq = (const float*)d_in[4];  const float* bq = (const float*)d_in[5];
    const float* Wk = (const float*)d_in[6];  const float* bk = (const float*)d_in[7];
    const float* Wv = (const float*)d_in[8];  const float* bv = (const float*)d_in[9];
    const float* Wo = (const float*)d_in[10]; const float* bo = (const float*)d_in[11];
    const float* We = (const float*)d_in[12]; const float* be = (const float*)d_in[13];
    const float* n1w = (const float*)d_in[14]; const float* n1b = (const float*)d_in[15];
    const float* W1 = (const float*)d_in[16]; const float* b1 = (const float*)d_in[17];
    const float* W2 = (const float*)d_in[18]; const float* b2 = (const float*)d_in[19];
    const float* n2w = (const float*)d_in[20]; const float* n2b = (const float*)d_in[21];
    float* out = (float*)d_out;

    float *Qp, *Kp, *Vp, *projp, *h1p, *f2p;
    cudaGetSymbolAddress((void**)&Qp, g_Q);
    cudaGetSymbolAddress((void**)&Kp, g_K);
    cudaGetSymbolAddress((void**)&Vp, g_V);
    cudaGetSymbolAddress((void**)&projp, g_proj);
    cudaGetSymbolAddress((void**)&h1p, g_h1);
    cudaGetSymbolAddress((void**)&f2p, g_f2);
    __nv_bfloat16 *nfH, *nfL, *WqH, *WqL, *WkH, *WkL, *WvH, *WvL, *WoH, *WoL,
                  *W1H, *W1L, *W2H, *W2L, *attH, *attL, *h1H, *h1L, *f1H, *f1L;
    cudaGetSymbolAddress((void**)&nfH, g_nfH);   cudaGetSymbolAddress((void**)&nfL, g_nfL);
    cudaGetSymbolAddress((void**)&WqH, g_WqH);   cudaGetSymbolAddress((void**)&WqL, g_WqL);
    cudaGetSymbolAddress((void**)&WkH, g_WkH);   cudaGetSymbolAddress((void**)&WkL, g_WkL);
    cudaGetSymbolAddress((void**)&WvH, g_WvH);   cudaGetSymbolAddress((void**)&WvL, g_WvL);
    cudaGetSymbolAddress((void**)&WoH, g_WoH);   cudaGetSymbolAddress((void**)&WoL, g_WoL);
    cudaGetSymbolAddress((void**)&W1H, g_W1H);   cudaGetSymbolAddress((void**)&W1L, g_W1L);
    cudaGetSymbolAddress((void**)&W2H, g_W2H);   cudaGetSymbolAddress((void**)&W2L, g_W2L);
    cudaGetSymbolAddress((void**)&attH, g_attH); cudaGetSymbolAddress((void**)&attL, g_attL);
    cudaGetSymbolAddress((void**)&h1H, g_h1H);   cudaGetSymbolAddress((void**)&h1L, g_h1L);
    cudaGetSymbolAddress((void**)&f1H, g_f1H);   cudaGetSymbolAddress((void**)&f1L, g_f1L);

    prep_scatter_kernel<<<1280, 256>>>(node_feat, Wq, Wk, Wv, Wo, W1, W2,
                                       src, dst, edge_feat, We, be);

    // QKV fused (z = weight select). grid (4,32,3)=384
    gemm_tc<<<dim3(DD / 64, NN / 64, 3), 128>>>(
        nfH, nfL, WqH, WkH, WvH, WqL, WkL, WvL, bq, bk, bv,
        Qp, Kp, Vp, nullptr, nullptr, DD, DD, 8);

    attn_kernel<<<NN, 256>>>();

    // Wo: split-K=2 into slice buffers. grid (4,32,2)=256
    gemm_tc<<<dim3(DD / 64, NN / 64, 2), 128>>>(
        attH, attL, WoH, WoH, WoH, WoL, WoL, WoL, bo, bo, bo,
        projp, nullptr, nullptr, nullptr, nullptr, DD, DD, 2);

    add_ln_kernel<<<NN, 256>>>(projp, 2, node_feat, bo, n1w, n1b, h1p, h1H, h1L, 1);

    // FFN1: bias+relu, bf16 pair out. grid (16,32)=512
    gemm_tc<<<dim3(DFF / 64, NN / 64, 1), 128>>>(
        h1H, h1L, W1H, W1H, W1H, W1L, W1L, W1L, b1, b1, b1,
        nullptr, nullptr, nullptr, f1H, f1L, DD, DFF, 1 | 4);

    // FFN2: split-K=2 into slice buffers. grid (4,32,2)=256
    gemm_tc<<<dim3(DD / 64, NN / 64, 2), 128>>>(
        f1H, f1L, W2H, W2H, W2H, W2L, W2L, W2L, b2, b2, b2,
        f2p, nullptr, nullptr, nullptr, nullptr, DFF, DD, 2);

    add_ln_kernel<<<NN, 256>>>(f2p, 2, h1p, b2, n2w, n2b, out, nullptr, nullptr, 0);
}